// round 11
// baseline (speedup 1.0000x reference)
#include <cuda_runtime.h>
#include <cuda_bf16.h>
#include <cstdint>
#include <math.h>

// Problem constants
#define DIM   1024
#define SEQ   2048
#define BATCH 2
#define NHEAD 16
#define HD    64
#define ROWS  (BATCH * SEQ)   // 4096

// ---------------------------------------------------------------------------
// PTX helpers (sm_80-portable only; no arch-'a' features)
// ---------------------------------------------------------------------------
__device__ __forceinline__ uint32_t smem_u32(const void* p) {
    uint32_t a;
    asm("{ .reg .u64 t; cvta.to.shared.u64 t, %1; cvt.u32.u64 %0, t; }" : "=r"(a) : "l"(p));
    return a;
}
#define CP_ASYNC16(sm, g) \
    asm volatile("cp.async.cg.shared.global [%0], [%1], 16;" :: "r"((uint32_t)(sm)), "l"(g) : "memory")
#define CP_COMMIT() asm volatile("cp.async.commit_group;" ::: "memory")
#define CP_WAIT1()  asm volatile("cp.async.wait_group 1;" ::: "memory")
#define CP_WAIT0()  asm volatile("cp.async.wait_group 0;" ::: "memory")

#define LDSM_X4(R, addr) \
    asm volatile("ldmatrix.sync.aligned.m8n8.x4.shared.b16 {%0,%1,%2,%3}, [%4];" \
        : "=r"((R)[0]), "=r"((R)[1]), "=r"((R)[2]), "=r"((R)[3]) : "r"((uint32_t)(addr)))
#define LDSM_X4_T(R, addr) \
    asm volatile("ldmatrix.sync.aligned.m8n8.x4.trans.shared.b16 {%0,%1,%2,%3}, [%4];" \
        : "=r"((R)[0]), "=r"((R)[1]), "=r"((R)[2]), "=r"((R)[3]) : "r"((uint32_t)(addr)))

// bf16 mma.sync m16n8k16, fp32 accumulate
__device__ __forceinline__ void mma16816(float* c, const uint32_t* a, const uint32_t* b) {
    asm volatile(
        "mma.sync.aligned.m16n8k16.row.col.f32.bf16.bf16.f32 "
        "{%0,%1,%2,%3}, {%4,%5,%6,%7}, {%8,%9}, {%0,%1,%2,%3};"
        : "+f"(c[0]), "+f"(c[1]), "+f"(c[2]), "+f"(c[3])
        : "r"(a[0]), "r"(a[1]), "r"(a[2]), "r"(a[3]), "r"(b[0]), "r"(b[1]));
}

__device__ __forceinline__ uint32_t pack2bf(__nv_bfloat16 a, __nv_bfloat16 b) {
    __nv_bfloat162 t(a, b);
    return *reinterpret_cast<uint32_t*>(&t);
}
__device__ __forceinline__ void split_bf16(float v, __nv_bfloat16& h, __nv_bfloat16& l) {
    h = __float2bfloat16(v);
    l = __float2bfloat16(v - __bfloat162float(h));
}

// ---------------------------------------------------------------------------
// Scratch (allocation-free rule: __device__ globals)
// ---------------------------------------------------------------------------
__device__ __nv_bfloat16 g_h1_hi[ROWS * DIM];
__device__ __nv_bfloat16 g_h1_lo[ROWS * DIM];
__device__ __nv_bfloat16 g_qkv_hi[ROWS * 3 * DIM];
__device__ __nv_bfloat16 g_qkv_lo[ROWS * 3 * DIM];
__device__ __nv_bfloat16 g_att_hi[ROWS * DIM];
__device__ __nv_bfloat16 g_att_lo[ROWS * DIM];
__device__ float         g_x2   [ROWS * DIM];
__device__ __nv_bfloat16 g_h2_hi[ROWS * DIM];
__device__ __nv_bfloat16 g_h2_lo[ROWS * DIM];
__device__ __nv_bfloat16 g_fc_hi[ROWS * 4 * DIM];
__device__ __nv_bfloat16 g_fc_lo[ROWS * 4 * DIM];
// Transposed weights [N, K] bf16 hi/lo
__device__ __nv_bfloat16 g_wqkv_hi[3 * DIM * DIM];
__device__ __nv_bfloat16 g_wqkv_lo[3 * DIM * DIM];
__device__ __nv_bfloat16 g_wproj_hi[DIM * DIM];
__device__ __nv_bfloat16 g_wproj_lo[DIM * DIM];
__device__ __nv_bfloat16 g_wfc_hi[4 * DIM * DIM];
__device__ __nv_bfloat16 g_wfc_lo[4 * DIM * DIM];
__device__ __nv_bfloat16 g_wout_hi[DIM * 4 * DIM];
__device__ __nv_bfloat16 g_wout_lo[DIM * 4 * DIM];

// ---------------------------------------------------------------------------
// Weight transpose + hi/lo split: W[K,N] fp32 -> Wt_hi/lo [N,K] bf16
// ---------------------------------------------------------------------------
__global__ void wconv_kernel(const float* __restrict__ W,
                             __nv_bfloat16* __restrict__ Wt_hi,
                             __nv_bfloat16* __restrict__ Wt_lo,
                             int K, int N) {
    __shared__ float t[32][33];
    const int tx = threadIdx.x & 31, ty = threadIdx.x >> 5;   // 32x8
    const int k0 = blockIdx.y * 32, n0 = blockIdx.x * 32;
    #pragma unroll
    for (int i = 0; i < 4; i++)
        t[ty + i * 8][tx] = W[(size_t)(k0 + ty + i * 8) * N + n0 + tx];
    __syncthreads();
    #pragma unroll
    for (int i = 0; i < 4; i++) {
        const int n = ty + i * 8;
        const float v = t[tx][n];
        __nv_bfloat16 h, l; split_bf16(v, h, l);
        const size_t o = (size_t)(n0 + n) * K + k0 + tx;
        Wt_hi[o] = h; Wt_lo[o] = l;
    }
}

// ---------------------------------------------------------------------------
// LayerNorm emitting hi/lo bf16
// ---------------------------------------------------------------------------
__global__ void ln_split_kernel(const float* __restrict__ x,
                                const float* __restrict__ gamma,
                                const float* __restrict__ beta,
                                __nv_bfloat16* __restrict__ hi,
                                __nv_bfloat16* __restrict__ lo) {
    const int row = blockIdx.x;
    const float* xr = x + (size_t)row * DIM;
    float4 v = ((const float4*)xr)[threadIdx.x];
    float s  = v.x + v.y + v.z + v.w;
    float s2 = v.x * v.x + v.y * v.y + v.z * v.z + v.w * v.w;
    #pragma unroll
    for (int o = 16; o > 0; o >>= 1) {
        s  += __shfl_down_sync(0xFFFFFFFFu, s,  o);
        s2 += __shfl_down_sync(0xFFFFFFFFu, s2, o);
    }
    __shared__ float rs[8], rs2[8];
    const int w = threadIdx.x >> 5, l = threadIdx.x & 31;
    if (l == 0) { rs[w] = s; rs2[w] = s2; }
    __syncthreads();
    if (threadIdx.x == 0) {
        float a = 0.f, b = 0.f;
        #pragma unroll
        for (int i = 0; i < 8; i++) { a += rs[i]; b += rs2[i]; }
        const float mu = a / DIM;
        rs[0] = mu; rs2[0] = b / DIM - mu * mu;
    }
    __syncthreads();
    const float mu  = rs[0];
    const float inv = rsqrtf(rs2[0] + 1e-5f);
    float4 gv = ((const float4*)gamma)[threadIdx.x];
    float4 bv = ((const float4*)beta )[threadIdx.x];
    float y0 = (v.x - mu) * inv * gv.x + bv.x;
    float y1 = (v.y - mu) * inv * gv.y + bv.y;
    float y2 = (v.z - mu) * inv * gv.z + bv.z;
    float y3 = (v.w - mu) * inv * gv.w + bv.w;
    __nv_bfloat16 h0, l0, h1, l1, h2, l2, h3, l3;
    split_bf16(y0, h0, l0); split_bf16(y1, h1, l1);
    split_bf16(y2, h2, l2); split_bf16(y3, h3, l3);
    const size_t o = (size_t)row * DIM + threadIdx.x * 4;
    *(__nv_bfloat162*)(hi + o)     = __nv_bfloat162(h0, h1);
    *(__nv_bfloat162*)(hi + o + 2) = __nv_bfloat162(h2, h3);
    *(__nv_bfloat162*)(lo + o)     = __nv_bfloat162(l0, l1);
    *(__nv_bfloat162*)(lo + o + 2) = __nv_bfloat162(l2, l3);
}

// ---------------------------------------------------------------------------
// mma.sync GEMM: C[M,N] = (A_hi+A_lo)[M,K] @ (B_hi+B_lo)^T  (B stored [N,K])
// CTA tile 128x128, 256 threads = 8 warps (2m x 4n), warp tile 64x32.
// Inner loop is pass-major per i-tile: 4 independent MMAs between any two
// same-accumulator HMMAs (avoids in-order-issue RAW stalls on the acc regs).
// EPI: 0 = fp32+bias, 1 = fp32+bias+resid, 2 = relu(x+bias)->hi/lo,
//      3 = (x+bias)->hi/lo
// ---------------------------------------------------------------------------
#define ROW_B    80
#define TILE_B   (128 * ROW_B)
#define STAGE_B  (4 * TILE_B)
#define GEMM_SMEM (2 * STAGE_B)

template <int EPI>
__global__ void __launch_bounds__(256, 2)
tc_gemm_kernel(const __nv_bfloat16* __restrict__ A_hi,
               const __nv_bfloat16* __restrict__ A_lo,
               const __nv_bfloat16* __restrict__ B_hi,
               const __nv_bfloat16* __restrict__ B_lo,
               const float* __restrict__ bias,
               const float* __restrict__ resid,
               float* __restrict__ C,
               __nv_bfloat16* __restrict__ C_hi,
               __nv_bfloat16* __restrict__ C_lo,
               int M, int N, int K) {
    extern __shared__ char smem[];
    const uint32_t sb = smem_u32(smem);
    const int tid = threadIdx.x, wid = tid >> 5, lid = tid & 31;
    const int g = lid >> 2, tig = lid & 3;
    const int wm = (wid & 1) * 64, wn = (wid >> 1) * 32;
    const int m0 = blockIdx.y * 128, n0 = blockIdx.x * 128;

    const __nv_bfloat16* parts[4] = { A_hi, A_lo, B_hi, B_lo };
    const int NC = K >> 5;

    auto load_chunk = [&](int kc, int s) {
        const int k0 = kc << 5;
        #pragma unroll
        for (int p = 0; p < 4; p++) {
            const __nv_bfloat16* src = parts[p];
            const int rbase = (p < 2) ? m0 : n0;
            const uint32_t pb = sb + s * STAGE_B + p * TILE_B;
            #pragma unroll
            for (int i = 0; i < 2; i++) {
                const int idx = i * 256 + tid;
                const int r = idx >> 2, c = idx & 3;
                const __nv_bfloat16* gp = src + (size_t)(rbase + r) * K + k0 + c * 8;
                CP_ASYNC16(pb + r * ROW_B + c * 16, gp);
            }
        }
        CP_COMMIT();
    };

    float acc[4][4][4] = {};

    load_chunk(0, 0);
    load_chunk(1, 1);

    for (int kc = 0; kc < NC; kc++) {
        CP_WAIT1();
        __syncthreads();
        const int s = kc & 1;
        const uint32_t Ah = sb + s * STAGE_B;
        const uint32_t Al = Ah + TILE_B;
        const uint32_t Bh = Ah + 2 * TILE_B;
        const uint32_t Bl = Ah + 3 * TILE_B;

        #pragma unroll
        for (int ks = 0; ks < 2; ks++) {
            const uint32_t kbyte = ks * 32 + tig * 4;
            uint32_t bh[4][2], bl[4][2];
            #pragma unroll
            for (int j = 0; j < 4; j++) {
                const uint32_t ro = (uint32_t)(wn + j * 8 + g) * ROW_B + kbyte;
                bh[j][0] = *(const uint32_t*)(smem + (Bh - sb) + ro);
                bh[j][1] = *(const uint32_t*)(smem + (Bh - sb) + ro + 16);
                bl[j][0] = *(const uint32_t*)(smem + (Bl - sb) + ro);
                bl[j][1] = *(const uint32_t*)(smem + (Bl - sb) + ro + 16);
            }
            #pragma unroll
            for (int i = 0; i < 4; i++) {
                const uint32_t ro = (uint32_t)(wm + i * 16 + g) * ROW_B + kbyte;
                uint32_t ah[4], al[4];
                ah[0] = *(const uint32_t*)(smem + (Ah - sb) + ro);
                ah[1] = *(const uint32_t*)(smem + (Ah - sb) + ro + 8 * ROW_B);
                ah[2] = *(const uint32_t*)(smem + (Ah - sb) + ro + 16);
                ah[3] = *(const uint32_t*)(smem + (Ah - sb) + ro + 8 * ROW_B + 16);
                al[0] = *(const uint32_t*)(smem + (Al - sb) + ro);
                al[1] = *(const uint32_t*)(smem + (Al - sb) + ro + 8 * ROW_B);
                al[2] = *(const uint32_t*)(smem + (Al - sb) + ro + 16);
                al[3] = *(const uint32_t*)(smem + (Al - sb) + ro + 8 * ROW_B + 16);
                // pass-major: 4 independent MMAs between same-acc reuses
                #pragma unroll
                for (int j = 0; j < 4; j++) mma16816(acc[i][j], ah, bh[j]);
                #pragma unroll
                for (int j = 0; j < 4; j++) mma16816(acc[i][j], ah, bl[j]);
                #pragma unroll
                for (int j = 0; j < 4; j++) mma16816(acc[i][j], al, bh[j]);
            }
        }
        __syncthreads();
        if (kc + 2 < NC) load_chunk(kc + 2, s);
        else             CP_COMMIT();
    }

    // Epilogue
    #pragma unroll
    for (int i = 0; i < 4; i++) {
        const int row0 = m0 + wm + i * 16 + g;
        #pragma unroll
        for (int j = 0; j < 4; j++) {
            const int col = n0 + wn + j * 8 + tig * 2;
            const float2 b2 = *(const float2*)(bias + col);
            float v00 = acc[i][j][0] + b2.x;
            float v01 = acc[i][j][1] + b2.y;
            float v10 = acc[i][j][2] + b2.x;
            float v11 = acc[i][j][3] + b2.y;
            if (EPI >= 2) {
                if (EPI == 2) {
                    v00 = fmaxf(v00, 0.f); v01 = fmaxf(v01, 0.f);
                    v10 = fmaxf(v10, 0.f); v11 = fmaxf(v11, 0.f);
                }
                __nv_bfloat16 h0, l0, h1, l1;
                split_bf16(v00, h0, l0); split_bf16(v01, h1, l1);
                *(__nv_bfloat162*)(C_hi + (size_t)row0 * N + col) = __nv_bfloat162(h0, h1);
                *(__nv_bfloat162*)(C_lo + (size_t)row0 * N + col) = __nv_bfloat162(l0, l1);
                split_bf16(v10, h0, l0); split_bf16(v11, h1, l1);
                *(__nv_bfloat162*)(C_hi + (size_t)(row0 + 8) * N + col) = __nv_bfloat162(h0, h1);
                *(__nv_bfloat162*)(C_lo + (size_t)(row0 + 8) * N + col) = __nv_bfloat162(l0, l1);
            } else {
                if (EPI == 1) {
                    const float2 r0 = *(const float2*)(resid + (size_t)row0 * N + col);
                    const float2 r1 = *(const float2*)(resid + (size_t)(row0 + 8) * N + col);
                    v00 += r0.x; v01 += r0.y; v10 += r1.x; v11 += r1.y;
                }
                *(float2*)(C + (size_t)row0 * N + col)       = make_float2(v00, v01);
                *(float2*)(C + (size_t)(row0 + 8) * N + col) = make_float2(v10, v11);
            }
        }
    }
}

// ---------------------------------------------------------------------------
// Causal flash attention, bf16 mma.sync with hi/lo compensation, hd=64.
// 256 threads (8 warps), 128 q-rows per CTA. Unchanged from R9 (1245 µs).
// ---------------------------------------------------------------------------
#define FROWB 144                    // 128B data + 16B pad per row
#define FTILE (64 * FROWB)           // one 64-row K or V tile
#define FQTILE (128 * FROWB)         // one 128-row Q tile
#define FSTAGE (4 * FTILE)           // Kh,Kl,Vh,Vl
#define FLASH_SMEM (2 * FSTAGE)      // 73728 (Q staging reuses this area)

__global__ void __launch_bounds__(256)
flash_kernel(const __nv_bfloat16* __restrict__ qkv_hi,
             const __nv_bfloat16* __restrict__ qkv_lo,
             __nv_bfloat16* __restrict__ out_hi,
             __nv_bfloat16* __restrict__ out_lo) {
    extern __shared__ char fsm[];
    const uint32_t sb = smem_u32(fsm);
    const int tid = threadIdx.x, wid = tid >> 5, lid = tid & 31;
    const int g = lid >> 2, tig = lid & 3;
    const int lt = lid >> 3, lr = lid & 7;
    const int b = blockIdx.y >> 4, h = blockIdx.y & 15;
    const int qt = blockIdx.x, q0 = qt * 128, wq = wid * 16;
    const size_t rstride = 3 * DIM;
    const __nv_bfloat16* qh_g = qkv_hi + (size_t)b * SEQ * rstride + h * HD;
    const __nv_bfloat16* ql_g = qkv_lo + (size_t)b * SEQ * rstride + h * HD;

    // ---- Stage Q hi/lo (128 rows), load A-fragments, then free the smem ----
    #pragma unroll
    for (int t = 0; t < 2; t++) {
        const __nv_bfloat16* src = t ? ql_g : qh_g;
        #pragma unroll
        for (int i = 0; i < 4; i++) {
            const int idx = i * 256 + tid;
            const int r = idx >> 3, c = idx & 7;
            CP_ASYNC16(sb + t * FQTILE + r * FROWB + c * 16,
                       src + (size_t)(q0 + r) * rstride + c * 8);
        }
    }
    CP_COMMIT();
    CP_WAIT0();
    __syncthreads();

    uint32_t qfh[4][4], qfl[4][4];
    {
        const int row = wq + ((lt & 1) ? 8 : 0) + lr;
        #pragma unroll
        for (int kc = 0; kc < 4; kc++) {
            const int col = kc * 16 + ((lt & 2) ? 8 : 0);
            LDSM_X4(qfh[kc], sb + row * FROWB + col * 2);
            LDSM_X4(qfl[kc], sb + FQTILE + row * FROWB + col * 2);
        }
    }
    __syncthreads();

    const __nv_bfloat16* srcs[4] = { qh_g + DIM, ql_g + DIM, qh_g + 2 * DIM, ql_g + 2 * DIM };
    auto load_kv = [&](int jt, int s) {
        const int kv0 = jt * 64;
        #pragma unroll
        for (int p = 0; p < 4; p++) {
            #pragma unroll
            for (int i = 0; i < 2; i++) {
                const int idx = i * 256 + tid;
                const int r = idx >> 3, c = idx & 7;
                CP_ASYNC16(sb + s * FSTAGE + p * FTILE + r * FROWB + c * 16,
                           srcs[p] + (size_t)(kv0 + r) * rstride + c * 8);
            }
        }
        CP_COMMIT();
    };

    float m0v = -1e30f, m1v = -1e30f, l0v = 0.f, l1v = 0.f;
    float oacc[8][4] = {};

    load_kv(0, 0);

    const int krow = ((lt & 2) ? 8 : 0) + lr;
    const int kcol8 = (lt & 1) ? 8 : 0;
    const int vrow = ((lt & 1) ? 8 : 0) + lr;
    const int vcol8 = (lt & 2) ? 8 : 0;

    const int NJT = 2 * qt + 2;                 // kv tiles covering [0, q0+128)
    for (int jt = 0; jt < NJT; jt++) {
        const int s = jt & 1;
        __syncthreads();
        if (jt + 1 < NJT) load_kv(jt + 1, s ^ 1);
        else              CP_COMMIT();
        CP_WAIT1();
        __syncthreads();

        const uint32_t Kh = sb + s * FSTAGE;
        const uint32_t Kl = Kh + FTILE;
        const uint32_t Vh = Kh + 2 * FTILE;
        const uint32_t Vl = Kh + 3 * FTILE;

        // ---- S = Q K^T (QhKh + QhKl + QlKh) ----
        float sacc[8][4] = {};
        #pragma unroll
        for (int kc = 0; kc < 4; kc++) {
            #pragma unroll
            for (int np = 0; np < 4; np++) {
                const uint32_t ko = (uint32_t)(np * 16 + krow) * FROWB + (kc * 16 + kcol8) * 2;
                uint32_t kb[4];
                LDSM_X4(kb, Kh + ko);
                mma16816(sacc[2 * np],     qfh[kc], kb);
                mma16816(sacc[2 * np + 1], qfh[kc], kb + 2);
                mma16816(sacc[2 * np],     qfl[kc], kb);
                mma16816(sacc[2 * np + 1], qfl[kc], kb + 2);
                LDSM_X4(kb, Kl + ko);
                mma16816(sacc[2 * np],     qfh[kc], kb);
                mma16816(sacc[2 * np + 1], qfh[kc], kb + 2);
            }
        }

        // ---- causal mask (last two kv tiles only) ----
        const int kv0 = jt * 64;
        const int row0 = q0 + wq + g, row1 = row0 + 8;
        if (jt >= 2 * qt) {
            #pragma unroll
            for (int j = 0; j < 8; j++) {
                const int cb = kv0 + j * 8 + tig * 2;
                if (cb > row0)     sacc[j][0] = -1e30f;
                if (cb + 1 > row0) sacc[j][1] = -1e30f;
                if (cb > row1)     sacc[j][2] = -1e30f;
                if (cb + 1 > row1) sacc[j][3] = -1e30f;
            }
        }

        // ---- online softmax ----
        float mx0 = m0v, mx1 = m1v;
        #pragma unroll
        for (int j = 0; j < 8; j++) {
            mx0 = fmaxf(mx0, fmaxf(sacc[j][0], sacc[j][1]));
            mx1 = fmaxf(mx1, fmaxf(sacc[j][2], sacc[j][3]));
        }
        mx0 = fmaxf(mx0, __shfl_xor_sync(0xFFFFFFFFu, mx0, 1));
        mx0 = fmaxf(mx0, __shfl_xor_sync(0xFFFFFFFFu, mx0, 2));
        mx1 = fmaxf(mx1, __shfl_xor_sync(0xFFFFFFFFu, mx1, 1));
        mx1 = fmaxf(mx1, __shfl_xor_sync(0xFFFFFFFFu, mx1, 2));
        const float al0 = __expf((m0v - mx0) * 0.125f);
        const float al1 = __expf((m1v - mx1) * 0.125f);
        m0v = mx0; m1v = mx1;

        float ls0 = 0.f, ls1 = 0.f;
        #pragma unroll
        for (int j = 0; j < 8; j++) {
            sacc[j][0] = __expf((sacc[j][0] - mx0) * 0.125f); ls0 += sacc[j][0];
            sacc[j][1] = __expf((sacc[j][1] - mx0) * 0.125f); ls0 += sacc[j][1];
            sacc[j][2] = __expf((sacc[j][2] - mx1) * 0.125f); ls1 += sacc[j][2];
            sacc[j][3] = __expf((sacc[j][3] - mx1) * 0.125f); ls1 += sacc[j][3];
        }
        ls0 += __shfl_xor_sync(0xFFFFFFFFu, ls0, 1);
        ls0 += __shfl_xor_sync(0xFFFFFFFFu, ls0, 2);
        ls1 += __shfl_xor_sync(0xFFFFFFFFu, ls1, 1);
        ls1 += __shfl_xor_sync(0xFFFFFFFFu, ls1, 2);
        l0v = l0v * al0 + ls0;
        l1v = l1v * al1 + ls1;

        #pragma unroll
        for (int j = 0; j < 8; j++) {
            oacc[j][0] *= al0; oacc[j][1] *= al0;
            oacc[j][2] *= al1; oacc[j][3] *= al1;
        }

        // ---- O += P V (PhVh + PhVl + PlVh) ----
        #pragma unroll
        for (int kk = 0; kk < 4; kk++) {
            uint32_t aph[4], apl[4];
            {
                __nv_bfloat16 h0, l0, h1, l1;
                split_bf16(sacc[2 * kk][0], h0, l0); split_bf16(sacc[2 * kk][1], h1, l1);
                aph[0] = pack2bf(h0, h1); apl[0] = pack2bf(l0, l1);
                split_bf16(sacc[2 * kk][2], h0, l0); split_bf16(sacc[2 * kk][3], h1, l1);
                aph[1] = pack2bf(h0, h1); apl[1] = pack2bf(l0, l1);
                split_bf16(sacc[2 * kk + 1][0], h0, l0); split_bf16(sacc[2 * kk + 1][1], h1, l1);
                aph[2] = pack2bf(h0, h1); apl[2] = pack2bf(l0, l1);
                split_bf16(sacc[2 * kk + 1][2], h0, l0); split_bf16(sacc[2 * kk + 1][3], h1, l1);
                aph[3] = pack2bf(h0, h1); apl[3] = pack2bf(l0, l1);
            }
            #pragma unroll
            for (int np = 0; np < 4; np++) {
                const uint32_t vo = (uint32_t)(kk * 16 + vrow) * FROWB + (np * 16 + vcol8) * 2;
                uint32_t vb[4];
                LDSM_X4_T(vb, Vh + vo);
                mma16816(oacc[2 * np],     aph, vb);
                mma16816(oacc[2 * np + 1], aph, vb + 2);
                mma16816(oacc[2 * np],     apl, vb);
                mma16816(oacc[2 * np + 1], apl, vb + 2);
                LDSM_X4_T(vb, Vl + vo);
                mma16816(oacc[2 * np],     aph, vb);
                mma16816(oacc[2 * np + 1], aph, vb + 2);
            }
        }
    }

    // ---- epilogue: divide by l, split hi/lo, store ----
    const float inv0 = 1.f / l0v, inv1 = 1.f / l1v;
    const size_t base0 = (size_t)(b * SEQ + q0 + wq + g) * DIM + h * HD;
    const size_t base1 = base0 + 8 * DIM;
    #pragma unroll
    for (int j = 0; j < 8; j++) {
        const int co = j * 8 + tig * 2;
        __nv_bfloat16 h0, lo0, h1, lo1;
        split_bf16(oacc[j][0] * inv0, h0, lo0);
        split_bf16(oacc[j][1] * inv0, h1, lo1);
        *(__nv_bfloat162*)(out_hi + base0 + co) = __nv_bfloat162(h0, h1);
        *(__nv_bfloat162*)(out_lo + base0 + co) = __nv_bfloat162(lo0, lo1);
        split_bf16(oacc[j][2] * inv1, h0, lo0);
        split_bf16(oacc[j][3] * inv1, h1, lo1);
        *(__nv_bfloat162*)(out_hi + base1 + co) = __nv_bfloat162(h0, h1);
        *(__nv_bfloat162*)(out_lo + base1 + co) = __nv_bfloat162(lo0, lo1);
    }
}

// ---------------------------------------------------------------------------
// Launch
// ---------------------------------------------------------------------------
extern "C" void kernel_launch(void* const* d_in, const int* in_sizes, int n_in,
                              void* d_out, int out_size) {
    const float* x      = (const float*)d_in[0];
    const float* ln1_g  = (const float*)d_in[1];
    const float* ln1_b  = (const float*)d_in[2];
    const float* ln2_g  = (const float*)d_in[3];
    const float* ln2_b  = (const float*)d_in[4];
    const float* W_qkv  = (const float*)d_in[5];
    const float* b_qkv  = (const float*)d_in[6];
    const float* W_proj = (const float*)d_in[7];
    const float* b_proj = (const float*)d_in[8];
    const float* W_fc   = (const float*)d_in[9];
    const float* b_fc   = (const float*)d_in[10];
    const float* W_out  = (const float*)d_in[11];
    const float* b_out  = (const float*)d_in[12];
    float* out = (float*)d_out;

    __nv_bfloat16 *h1h, *h1l, *qkvh, *qkvl, *atth, *attl, *h2h, *h2l, *fch, *fcl;
    __nv_bfloat16 *wqh, *wql, *wph, *wpl, *wfh, *wfl, *woh, *wol;
    float *x2;
    cudaGetSymbolAddress((void**)&h1h, g_h1_hi);  cudaGetSymbolAddress((void**)&h1l, g_h1_lo);
    cudaGetSymbolAddress((void**)&qkvh, g_qkv_hi); cudaGetSymbolAddress((void**)&qkvl, g_qkv_lo);
    cudaGetSymbolAddress((void**)&atth, g_att_hi); cudaGetSymbolAddress((void**)&attl, g_att_lo);
    cudaGetSymbolAddress((void**)&x2,  g_x2);
    cudaGetSymbolAddress((void**)&h2h, g_h2_hi);  cudaGetSymbolAddress((void**)&h2l, g_h2_lo);
    cudaGetSymbolAddress((void**)&fch, g_fc_hi);  cudaGetSymbolAddress((void**)&fcl, g_fc_lo);
    cudaGetSymbolAddress((void**)&wqh, g_wqkv_hi); cudaGetSymbolAddress((void**)&wql, g_wqkv_lo);
    cudaGetSymbolAddress((void**)&wph, g_wproj_hi); cudaGetSymbolAddress((void**)&wpl, g_wproj_lo);
    cudaGetSymbolAddress((void**)&wfh, g_wfc_hi);  cudaGetSymbolAddress((void**)&wfl, g_wfc_lo);
    cudaGetSymbolAddress((void**)&woh, g_wout_hi); cudaGetSymbolAddress((void**)&wol, g_wout_lo);

    cudaFuncSetAttribute(tc_gemm_kernel<0>, cudaFuncAttributeMaxDynamicSharedMemorySize, GEMM_SMEM);
    cudaFuncSetAttribute(tc_gemm_kernel<1>, cudaFuncAttributeMaxDynamicSharedMemorySize, GEMM_SMEM);
    cudaFuncSetAttribute(tc_gemm_kernel<2>, cudaFuncAttributeMaxDynamicSharedMemorySize, GEMM_SMEM);
    cudaFuncSetAttribute(tc_gemm_kernel<3>, cudaFuncAttributeMaxDynamicSharedMemorySize, GEMM_SMEM);
    cudaFuncSetAttribute(flash_kernel, cudaFuncAttributeMaxDynamicSharedMemorySize, FLASH_SMEM);

    // Weight transpose + split
    wconv_kernel<<<dim3(3 * DIM / 32, DIM / 32), 256>>>(W_qkv, wqh, wql, DIM, 3 * DIM);
    wconv_kernel<<<dim3(DIM / 32, DIM / 32), 256>>>(W_proj, wph, wpl, DIM, DIM);
    wconv_kernel<<<dim3(4 * DIM / 32, DIM / 32), 256>>>(W_fc, wfh, wfl, DIM, 4 * DIM);
    wconv_kernel<<<dim3(DIM / 32, 4 * DIM / 32), 256>>>(W_out, woh, wol, 4 * DIM, DIM);

    // 1) h1 = LN1(x) -> hi/lo
    ln_split_kernel<<<ROWS, 256>>>(x, ln1_g, ln1_b, h1h, h1l);

    // 2) qkv = h1 @ W_qkv + b_qkv -> hi/lo bf16 directly
    tc_gemm_kernel<3><<<dim3(3 * DIM / 128, ROWS / 128), 256, GEMM_SMEM>>>(
        h1h, h1l, wqh, wql, b_qkv, nullptr, nullptr, qkvh, qkvl, ROWS, 3 * DIM, DIM);

    // 3) att = causal_attention(qkv) -> hi/lo bf16 directly
    flash_kernel<<<dim3(SEQ / 128, BATCH * NHEAD), 256, FLASH_SMEM>>>(qkvh, qkvl, atth, attl);

    // 4) x2 = att @ W_proj + b_proj + x
    tc_gemm_kernel<1><<<dim3(DIM / 128, ROWS / 128), 256, GEMM_SMEM>>>(
        atth, attl, wph, wpl, b_proj, x, x2, nullptr, nullptr, ROWS, DIM, DIM);

    // 5) h2 = LN2(x2) -> hi/lo
    ln_split_kernel<<<ROWS, 256>>>(x2, ln2_g, ln2_b, h2h, h2l);

    // 6) fc = relu(h2 @ W_fc + b_fc) -> hi/lo
    tc_gemm_kernel<2><<<dim3(4 * DIM / 128, ROWS / 128), 256, GEMM_SMEM>>>(
        h2h, h2l, wfh, wfl, b_fc, nullptr, nullptr, fch, fcl, ROWS, 4 * DIM, DIM);

    // 7) out = fc @ W_out + b_out + x2
    tc_gemm_kernel<1><<<dim3(DIM / 128, ROWS / 128), 256, GEMM_SMEM>>>(
        fch, fcl, woh, wol, b_out, x2, out, nullptr, nullptr, ROWS, DIM, 4 * DIM);
}

// round 12
// speedup vs baseline: 1.1782x; 1.1782x over previous
#include <cuda_runtime.h>
#include <cuda_bf16.h>
#include <cuda_fp16.h>
#include <cstdint>
#include <math.h>

// Problem constants
#define DIM   1024
#define SEQ   2048
#define BATCH 2
#define NHEAD 16
#define HD    64
#define ROWS  (BATCH * SEQ)   // 4096

// ---------------------------------------------------------------------------
// PTX helpers (sm_80-portable only; no arch-'a' features)
// ---------------------------------------------------------------------------
__device__ __forceinline__ uint32_t smem_u32(const void* p) {
    uint32_t a;
    asm("{ .reg .u64 t; cvta.to.shared.u64 t, %1; cvt.u32.u64 %0, t; }" : "=r"(a) : "l"(p));
    return a;
}
#define CP_ASYNC16(sm, g) \
    asm volatile("cp.async.cg.shared.global [%0], [%1], 16;" :: "r"((uint32_t)(sm)), "l"(g) : "memory")
#define CP_COMMIT() asm volatile("cp.async.commit_group;" ::: "memory")
#define CP_WAIT1()  asm volatile("cp.async.wait_group 1;" ::: "memory")
#define CP_WAIT0()  asm volatile("cp.async.wait_group 0;" ::: "memory")

#define LDSM_X4(R, addr) \
    asm volatile("ldmatrix.sync.aligned.m8n8.x4.shared.b16 {%0,%1,%2,%3}, [%4];" \
        : "=r"((R)[0]), "=r"((R)[1]), "=r"((R)[2]), "=r"((R)[3]) : "r"((uint32_t)(addr)))
#define LDSM_X4_T(R, addr) \
    asm volatile("ldmatrix.sync.aligned.m8n8.x4.trans.shared.b16 {%0,%1,%2,%3}, [%4];" \
        : "=r"((R)[0]), "=r"((R)[1]), "=r"((R)[2]), "=r"((R)[3]) : "r"((uint32_t)(addr)))

// bf16 mma.sync m16n8k16, fp32 accumulate
__device__ __forceinline__ void mma16816(float* c, const uint32_t* a, const uint32_t* b) {
    asm volatile(
        "mma.sync.aligned.m16n8k16.row.col.f32.bf16.bf16.f32 "
        "{%0,%1,%2,%3}, {%4,%5,%6,%7}, {%8,%9}, {%0,%1,%2,%3};"
        : "+f"(c[0]), "+f"(c[1]), "+f"(c[2]), "+f"(c[3])
        : "r"(a[0]), "r"(a[1]), "r"(a[2]), "r"(a[3]), "r"(b[0]), "r"(b[1]));
}
// fp16 mma.sync m16n8k16, fp32 accumulate
__device__ __forceinline__ void mma16816h(float* c, const uint32_t* a, const uint32_t* b) {
    asm volatile(
        "mma.sync.aligned.m16n8k16.row.col.f32.f16.f16.f32 "
        "{%0,%1,%2,%3}, {%4,%5,%6,%7}, {%8,%9}, {%0,%1,%2,%3};"
        : "+f"(c[0]), "+f"(c[1]), "+f"(c[2]), "+f"(c[3])
        : "r"(a[0]), "r"(a[1]), "r"(a[2]), "r"(a[3]), "r"(b[0]), "r"(b[1]));
}

__device__ __forceinline__ uint32_t pack2bf(__nv_bfloat16 a, __nv_bfloat16 b) {
    __nv_bfloat162 t(a, b);
    return *reinterpret_cast<uint32_t*>(&t);
}
__device__ __forceinline__ void split_bf16(float v, __nv_bfloat16& h, __nv_bfloat16& l) {
    h = __float2bfloat16(v);
    l = __float2bfloat16(v - __bfloat162float(h));
}
__device__ __forceinline__ void split_fp16(float v, __half& h, __half& l) {
    h = __float2half_rn(v);
    l = __float2half_rn(v - __half2float(h));
}

// ---------------------------------------------------------------------------
// Scratch (allocation-free rule: __device__ globals)
// ---------------------------------------------------------------------------
__device__ __nv_bfloat16 g_h1_hi[ROWS * DIM];
__device__ __nv_bfloat16 g_h1_lo[ROWS * DIM];
__device__ __nv_bfloat16 g_qkv_hi[ROWS * 3 * DIM];
__device__ __nv_bfloat16 g_qkv_lo[ROWS * 3 * DIM];
__device__ __nv_bfloat16 g_att_hi[ROWS * DIM];
__device__ __nv_bfloat16 g_att_lo[ROWS * DIM];
__device__ float         g_x2   [ROWS * DIM];
__device__ __half        g_h2_hi[ROWS * DIM];
__device__ __half        g_h2_lo[ROWS * DIM];
__device__ __half        g_fc_hi[ROWS * 4 * DIM];
__device__ __half        g_fc_lo[ROWS * 4 * DIM];
// Transposed weights [N, K]
__device__ __nv_bfloat16 g_wqkv_hi[3 * DIM * DIM];
__device__ __nv_bfloat16 g_wqkv_lo[3 * DIM * DIM];
__device__ __nv_bfloat16 g_wproj_hi[DIM * DIM];
__device__ __nv_bfloat16 g_wproj_lo[DIM * DIM];
__device__ __half        g_wfc_h [4 * DIM * DIM];   // fp16 single
__device__ __half        g_wout_h[DIM * 4 * DIM];   // fp16 single

// ---------------------------------------------------------------------------
// Weight transpose + hi/lo split: W[K,N] fp32 -> Wt_hi/lo [N,K] bf16
// ---------------------------------------------------------------------------
__global__ void wconv_kernel(const float* __restrict__ W,
                             __nv_bfloat16* __restrict__ Wt_hi,
                             __nv_bfloat16* __restrict__ Wt_lo,
                             int K, int N) {
    __shared__ float t[32][33];
    const int tx = threadIdx.x & 31, ty = threadIdx.x >> 5;   // 32x8
    const int k0 = blockIdx.y * 32, n0 = blockIdx.x * 32;
    #pragma unroll
    for (int i = 0; i < 4; i++)
        t[ty + i * 8][tx] = W[(size_t)(k0 + ty + i * 8) * N + n0 + tx];
    __syncthreads();
    #pragma unroll
    for (int i = 0; i < 4; i++) {
        const int n = ty + i * 8;
        const float v = t[tx][n];
        __nv_bfloat16 h, l; split_bf16(v, h, l);
        const size_t o = (size_t)(n0 + n) * K + k0 + tx;
        Wt_hi[o] = h; Wt_lo[o] = l;
    }
}

// Weight transpose, single fp16: W[K,N] fp32 -> Wt [N,K] fp16
__global__ void wconv_h_kernel(const float* __restrict__ W,
                               __half* __restrict__ Wt,
                               int K, int N) {
    __shared__ float t[32][33];
    const int tx = threadIdx.x & 31, ty = threadIdx.x >> 5;
    const int k0 = blockIdx.y * 32, n0 = blockIdx.x * 32;
    #pragma unroll
    for (int i = 0; i < 4; i++)
        t[ty + i * 8][tx] = W[(size_t)(k0 + ty + i * 8) * N + n0 + tx];
    __syncthreads();
    #pragma unroll
    for (int i = 0; i < 4; i++) {
        const int n = ty + i * 8;
        Wt[(size_t)(n0 + n) * K + k0 + tx] = __float2half_rn(t[tx][n]);
    }
}

// ---------------------------------------------------------------------------
// LayerNorm emitting hi/lo bf16
// ---------------------------------------------------------------------------
__global__ void ln_split_kernel(const float* __restrict__ x,
                                const float* __restrict__ gamma,
                                const float* __restrict__ beta,
                                __nv_bfloat16* __restrict__ hi,
                                __nv_bfloat16* __restrict__ lo) {
    const int row = blockIdx.x;
    const float* xr = x + (size_t)row * DIM;
    float4 v = ((const float4*)xr)[threadIdx.x];
    float s  = v.x + v.y + v.z + v.w;
    float s2 = v.x * v.x + v.y * v.y + v.z * v.z + v.w * v.w;
    #pragma unroll
    for (int o = 16; o > 0; o >>= 1) {
        s  += __shfl_down_sync(0xFFFFFFFFu, s,  o);
        s2 += __shfl_down_sync(0xFFFFFFFFu, s2, o);
    }
    __shared__ float rs[8], rs2[8];
    const int w = threadIdx.x >> 5, l = threadIdx.x & 31;
    if (l == 0) { rs[w] = s; rs2[w] = s2; }
    __syncthreads();
    if (threadIdx.x == 0) {
        float a = 0.f, b = 0.f;
        #pragma unroll
        for (int i = 0; i < 8; i++) { a += rs[i]; b += rs2[i]; }
        const float mu = a / DIM;
        rs[0] = mu; rs2[0] = b / DIM - mu * mu;
    }
    __syncthreads();
    const float mu  = rs[0];
    const float inv = rsqrtf(rs2[0] + 1e-5f);
    float4 gv = ((const float4*)gamma)[threadIdx.x];
    float4 bv = ((const float4*)beta )[threadIdx.x];
    float y0 = (v.x - mu) * inv * gv.x + bv.x;
    float y1 = (v.y - mu) * inv * gv.y + bv.y;
    float y2 = (v.z - mu) * inv * gv.z + bv.z;
    float y3 = (v.w - mu) * inv * gv.w + bv.w;
    __nv_bfloat16 h0, l0, h1, l1, h2, l2, h3, l3;
    split_bf16(y0, h0, l0); split_bf16(y1, h1, l1);
    split_bf16(y2, h2, l2); split_bf16(y3, h3, l3);
    const size_t o = (size_t)row * DIM + threadIdx.x * 4;
    *(__nv_bfloat162*)(hi + o)     = __nv_bfloat162(h0, h1);
    *(__nv_bfloat162*)(hi + o + 2) = __nv_bfloat162(h2, h3);
    *(__nv_bfloat162*)(lo + o)     = __nv_bfloat162(l0, l1);
    *(__nv_bfloat162*)(lo + o + 2) = __nv_bfloat162(l2, l3);
}

// LayerNorm emitting hi/lo fp16 (for the fp16 2-pass MLP path)
__global__ void ln_split_h_kernel(const float* __restrict__ x,
                                  const float* __restrict__ gamma,
                                  const float* __restrict__ beta,
                                  __half* __restrict__ hi,
                                  __half* __restrict__ lo) {
    const int row = blockIdx.x;
    const float* xr = x + (size_t)row * DIM;
    float4 v = ((const float4*)xr)[threadIdx.x];
    float s  = v.x + v.y + v.z + v.w;
    float s2 = v.x * v.x + v.y * v.y + v.z * v.z + v.w * v.w;
    #pragma unroll
    for (int o = 16; o > 0; o >>= 1) {
        s  += __shfl_down_sync(0xFFFFFFFFu, s,  o);
        s2 += __shfl_down_sync(0xFFFFFFFFu, s2, o);
    }
    __shared__ float rs[8], rs2[8];
    const int w = threadIdx.x >> 5, l = threadIdx.x & 31;
    if (l == 0) { rs[w] = s; rs2[w] = s2; }
    __syncthreads();
    if (threadIdx.x == 0) {
        float a = 0.f, b = 0.f;
        #pragma unroll
        for (int i = 0; i < 8; i++) { a += rs[i]; b += rs2[i]; }
        const float mu = a / DIM;
        rs[0] = mu; rs2[0] = b / DIM - mu * mu;
    }
    __syncthreads();
    const float mu  = rs[0];
    const float inv = rsqrtf(rs2[0] + 1e-5f);
    float4 gv = ((const float4*)gamma)[threadIdx.x];
    float4 bv = ((const float4*)beta )[threadIdx.x];
    float y0 = (v.x - mu) * inv * gv.x + bv.x;
    float y1 = (v.y - mu) * inv * gv.y + bv.y;
    float y2 = (v.z - mu) * inv * gv.z + bv.z;
    float y3 = (v.w - mu) * inv * gv.w + bv.w;
    __half h0, l0, h1, l1, h2, l2, h3, l3;
    split_fp16(y0, h0, l0); split_fp16(y1, h1, l1);
    split_fp16(y2, h2, l2); split_fp16(y3, h3, l3);
    const size_t o = (size_t)row * DIM + threadIdx.x * 4;
    *(__half2*)(hi + o)     = __half2(h0, h1);
    *(__half2*)(hi + o + 2) = __half2(h2, h3);
    *(__half2*)(lo + o)     = __half2(l0, l1);
    *(__half2*)(lo + o + 2) = __half2(l2, l3);
}

// ---------------------------------------------------------------------------
// bf16 3-pass mma.sync GEMM (R6 structure — proven fastest)
// EPI: 1 = fp32+bias+resid, 3 = (x+bias)->hi/lo bf16
// ---------------------------------------------------------------------------
#define ROW_B    80
#define TILE_B   (128 * ROW_B)
#define STAGE_B  (4 * TILE_B)
#define GEMM_SMEM (2 * STAGE_B)

template <int EPI>
__global__ void __launch_bounds__(256, 2)
tc_gemm_kernel(const __nv_bfloat16* __restrict__ A_hi,
               const __nv_bfloat16* __restrict__ A_lo,
               const __nv_bfloat16* __restrict__ B_hi,
               const __nv_bfloat16* __restrict__ B_lo,
               const float* __restrict__ bias,
               const float* __restrict__ resid,
               float* __restrict__ C,
               __nv_bfloat16* __restrict__ C_hi,
               __nv_bfloat16* __restrict__ C_lo,
               int M, int N, int K) {
    extern __shared__ char smem[];
    const uint32_t sb = smem_u32(smem);
    const int tid = threadIdx.x, wid = tid >> 5, lid = tid & 31;
    const int g = lid >> 2, tig = lid & 3;
    const int wm = (wid & 1) * 64, wn = (wid >> 1) * 32;
    const int m0 = blockIdx.y * 128, n0 = blockIdx.x * 128;

    const __nv_bfloat16* parts[4] = { A_hi, A_lo, B_hi, B_lo };
    const int NC = K >> 5;

    auto load_chunk = [&](int kc, int s) {
        const int k0 = kc << 5;
        #pragma unroll
        for (int p = 0; p < 4; p++) {
            const __nv_bfloat16* src = parts[p];
            const int rbase = (p < 2) ? m0 : n0;
            const uint32_t pb = sb + s * STAGE_B + p * TILE_B;
            #pragma unroll
            for (int i = 0; i < 2; i++) {
                const int idx = i * 256 + tid;
                const int r = idx >> 2, c = idx & 3;
                const __nv_bfloat16* gp = src + (size_t)(rbase + r) * K + k0 + c * 8;
                CP_ASYNC16(pb + r * ROW_B + c * 16, gp);
            }
        }
        CP_COMMIT();
    };

    float acc[4][4][4] = {};

    load_chunk(0, 0);
    load_chunk(1, 1);

    for (int kc = 0; kc < NC; kc++) {
        CP_WAIT1();
        __syncthreads();
        const int s = kc & 1;
        const uint32_t Ah = sb + s * STAGE_B;
        const uint32_t Al = Ah + TILE_B;
        const uint32_t Bh = Ah + 2 * TILE_B;
        const uint32_t Bl = Ah + 3 * TILE_B;

        #pragma unroll
        for (int ks = 0; ks < 2; ks++) {
            const uint32_t kbyte = ks * 32 + tig * 4;
            uint32_t bh[4][2], bl[4][2];
            #pragma unroll
            for (int j = 0; j < 4; j++) {
                const uint32_t ro = (uint32_t)(wn + j * 8 + g) * ROW_B + kbyte;
                bh[j][0] = *(const uint32_t*)(smem + (Bh - sb) + ro);
                bh[j][1] = *(const uint32_t*)(smem + (Bh - sb) + ro + 16);
                bl[j][0] = *(const uint32_t*)(smem + (Bl - sb) + ro);
                bl[j][1] = *(const uint32_t*)(smem + (Bl - sb) + ro + 16);
            }
            #pragma unroll
            for (int i = 0; i < 4; i++) {
                const uint32_t ro = (uint32_t)(wm + i * 16 + g) * ROW_B + kbyte;
                uint32_t ah[4], al[4];
                ah[0] = *(const uint32_t*)(smem + (Ah - sb) + ro);
                ah[1] = *(const uint32_t*)(smem + (Ah - sb) + ro + 8 * ROW_B);
                ah[2] = *(const uint32_t*)(smem + (Ah - sb) + ro + 16);
                ah[3] = *(const uint32_t*)(smem + (Ah - sb) + ro + 8 * ROW_B + 16);
                al[0] = *(const uint32_t*)(smem + (Al - sb) + ro);
                al[1] = *(const uint32_t*)(smem + (Al - sb) + ro + 8 * ROW_B);
                al[2] = *(const uint32_t*)(smem + (Al - sb) + ro + 16);
                al[3] = *(const uint32_t*)(smem + (Al - sb) + ro + 8 * ROW_B + 16);
                #pragma unroll
                for (int j = 0; j < 4; j++) {
                    mma16816(acc[i][j], ah, bh[j]);
                    mma16816(acc[i][j], ah, bl[j]);
                    mma16816(acc[i][j], al, bh[j]);
                }
            }
        }
        __syncthreads();
        if (kc + 2 < NC) load_chunk(kc + 2, s);
        else             CP_COMMIT();
    }

    // Epilogue
    #pragma unroll
    for (int i = 0; i < 4; i++) {
        const int row0 = m0 + wm + i * 16 + g;
        #pragma unroll
        for (int j = 0; j < 4; j++) {
            const int col = n0 + wn + j * 8 + tig * 2;
            const float2 b2 = *(const float2*)(bias + col);
            float v00 = acc[i][j][0] + b2.x;
            float v01 = acc[i][j][1] + b2.y;
            float v10 = acc[i][j][2] + b2.x;
            float v11 = acc[i][j][3] + b2.y;
            if (EPI == 3) {
                __nv_bfloat16 h0, l0, h1, l1;
                split_bf16(v00, h0, l0); split_bf16(v01, h1, l1);
                *(__nv_bfloat162*)(C_hi + (size_t)row0 * N + col) = __nv_bfloat162(h0, h1);
                *(__nv_bfloat162*)(C_lo + (size_t)row0 * N + col) = __nv_bfloat162(l0, l1);
                split_bf16(v10, h0, l0); split_bf16(v11, h1, l1);
                *(__nv_bfloat162*)(C_hi + (size_t)(row0 + 8) * N + col) = __nv_bfloat162(h0, h1);
                *(__nv_bfloat162*)(C_lo + (size_t)(row0 + 8) * N + col) = __nv_bfloat162(l0, l1);
            } else {
                if (EPI == 1) {
                    const float2 r0 = *(const float2*)(resid + (size_t)row0 * N + col);
                    const float2 r1 = *(const float2*)(resid + (size_t)(row0 + 8) * N + col);
                    v00 += r0.x; v01 += r0.y; v10 += r1.x; v11 += r1.y;
                }
                *(float2*)(C + (size_t)row0 * N + col)       = make_float2(v00, v01);
                *(float2*)(C + (size_t)(row0 + 8) * N + col) = make_float2(v10, v11);
            }
        }
    }
}

// ---------------------------------------------------------------------------
// fp16 2-pass GEMM: C[M,N] = (A_hi+A_lo)[M,K] @ B^T, B single fp16 [N,K].
// Exact in A; only error is B's fp16 rounding (2^-12). 8 MMAs per i-tile.
// EPI16: 0 = fp32+bias+resid, 1 = relu(x+bias)->hi/lo fp16
// ---------------------------------------------------------------------------
#define STAGE_H  (3 * TILE_B)        // Ah, Al, B
#define GEMM_SMEM_H (2 * STAGE_H)    // 61440

template <int EPI16>
__global__ void __launch_bounds__(256, 2)
tc_gemm_h_kernel(const __half* __restrict__ A_hi,
                 const __half* __restrict__ A_lo,
                 const __half* __restrict__ B,
                 const float* __restrict__ bias,
                 const float* __restrict__ resid,
                 float* __restrict__ C,
                 __half* __restrict__ C_hi,
                 __half* __restrict__ C_lo,
                 int M, int N, int K) {
    extern __shared__ char smem[];
    const uint32_t sb = smem_u32(smem);
    const int tid = threadIdx.x, wid = tid >> 5, lid = tid & 31;
    const int g = lid >> 2, tig = lid & 3;
    const int wm = (wid & 1) * 64, wn = (wid >> 1) * 32;
    const int m0 = blockIdx.y * 128, n0 = blockIdx.x * 128;

    const __half* parts[3] = { A_hi, A_lo, B };
    const int NC = K >> 5;

    auto load_chunk = [&](int kc, int s) {
        const int k0 = kc << 5;
        #pragma unroll
        for (int p = 0; p < 3; p++) {
            const __half* src = parts[p];
            const int rbase = (p < 2) ? m0 : n0;
            const uint32_t pb = sb + s * STAGE_H + p * TILE_B;
            #pragma unroll
            for (int i = 0; i < 2; i++) {
                const int idx = i * 256 + tid;
                const int r = idx >> 2, c = idx & 3;
                const __half* gp = src + (size_t)(rbase + r) * K + k0 + c * 8;
                CP_ASYNC16(pb + r * ROW_B + c * 16, gp);
            }
        }
        CP_COMMIT();
    };

    float acc[4][4][4] = {};

    load_chunk(0, 0);
    load_chunk(1, 1);

    for (int kc = 0; kc < NC; kc++) {
        CP_WAIT1();
        __syncthreads();
        const int s = kc & 1;
        const uint32_t Ah = sb + s * STAGE_H;
        const uint32_t Al = Ah + TILE_B;
        const uint32_t Bt = Ah + 2 * TILE_B;

        #pragma unroll
        for (int ks = 0; ks < 2; ks++) {
            const uint32_t kbyte = ks * 32 + tig * 4;
            uint32_t bf[4][2];
            #pragma unroll
            for (int j = 0; j < 4; j++) {
                const uint32_t ro = (uint32_t)(wn + j * 8 + g) * ROW_B + kbyte;
                bf[j][0] = *(const uint32_t*)(smem + (Bt - sb) + ro);
                bf[j][1] = *(const uint32_t*)(smem + (Bt - sb) + ro + 16);
            }
            #pragma unroll
            for (int i = 0; i < 4; i++) {
                const uint32_t ro = (uint32_t)(wm + i * 16 + g) * ROW_B + kbyte;
                uint32_t ah[4], al[4];
                ah[0] = *(const uint32_t*)(smem + (Ah - sb) + ro);
                ah[1] = *(const uint32_t*)(smem + (Ah - sb) + ro + 8 * ROW_B);
                ah[2] = *(const uint32_t*)(smem + (Ah - sb) + ro + 16);
                ah[3] = *(const uint32_t*)(smem + (Ah - sb) + ro + 8 * ROW_B + 16);
                al[0] = *(const uint32_t*)(smem + (Al - sb) + ro);
                al[1] = *(const uint32_t*)(smem + (Al - sb) + ro + 8 * ROW_B);
                al[2] = *(const uint32_t*)(smem + (Al - sb) + ro + 16);
                al[3] = *(const uint32_t*)(smem + (Al - sb) + ro + 8 * ROW_B + 16);
                #pragma unroll
                for (int j = 0; j < 4; j++) mma16816h(acc[i][j], ah, bf[j]);
                #pragma unroll
                for (int j = 0; j < 4; j++) mma16816h(acc[i][j], al, bf[j]);
            }
        }
        __syncthreads();
        if (kc + 2 < NC) load_chunk(kc + 2, s);
        else             CP_COMMIT();
    }

    // Epilogue
    #pragma unroll
    for (int i = 0; i < 4; i++) {
        const int row0 = m0 + wm + i * 16 + g;
        #pragma unroll
        for (int j = 0; j < 4; j++) {
            const int col = n0 + wn + j * 8 + tig * 2;
            const float2 b2 = *(const float2*)(bias + col);
            float v00 = acc[i][j][0] + b2.x;
            float v01 = acc[i][j][1] + b2.y;
            float v10 = acc[i][j][2] + b2.x;
            float v11 = acc[i][j][3] + b2.y;
            if (EPI16 == 1) {
                v00 = fmaxf(v00, 0.f); v01 = fmaxf(v01, 0.f);
                v10 = fmaxf(v10, 0.f); v11 = fmaxf(v11, 0.f);
                __half h0, l0, h1, l1;
                split_fp16(v00, h0, l0); split_fp16(v01, h1, l1);
                *(__half2*)(C_hi + (size_t)row0 * N + col) = __half2(h0, h1);
                *(__half2*)(C_lo + (size_t)row0 * N + col) = __half2(l0, l1);
                split_fp16(v10, h0, l0); split_fp16(v11, h1, l1);
                *(__half2*)(C_hi + (size_t)(row0 + 8) * N + col) = __half2(h0, h1);
                *(__half2*)(C_lo + (size_t)(row0 + 8) * N + col) = __half2(l0, l1);
            } else {
                const float2 r0 = *(const float2*)(resid + (size_t)row0 * N + col);
                const float2 r1 = *(const float2*)(resid + (size_t)(row0 + 8) * N + col);
                v00 += r0.x; v01 += r0.y; v10 += r1.x; v11 += r1.y;
                *(float2*)(C + (size_t)row0 * N + col)       = make_float2(v00, v01);
                *(float2*)(C + (size_t)(row0 + 8) * N + col) = make_float2(v10, v11);
            }
        }
    }
}

// ---------------------------------------------------------------------------
// Causal flash attention, bf16 mma.sync with hi/lo compensation, hd=64.
// 256 threads (8 warps), 128 q-rows per CTA. Unchanged from R9 (1245 µs).
// ---------------------------------------------------------------------------
#define FROWB 144                    // 128B data + 16B pad per row
#define FTILE (64 * FROWB)           // one 64-row K or V tile
#define FQTILE (128 * FROWB)         // one 128-row Q tile
#define FSTAGE (4 * FTILE)           // Kh,Kl,Vh,Vl
#define FLASH_SMEM (2 * FSTAGE)      // 73728 (Q staging reuses this area)

__global__ void __launch_bounds__(256)
flash_kernel(const __nv_bfloat16* __restrict__ qkv_hi,
             const __nv_bfloat16* __restrict__ qkv_lo,
             __nv_bfloat16* __restrict__ out_hi,
             __nv_bfloat16* __restrict__ out_lo) {
    extern __shared__ char fsm[];
    const uint32_t sb = smem_u32(fsm);
    const int tid = threadIdx.x, wid = tid >> 5, lid = tid & 31;
    const int g = lid >> 2, tig = lid & 3;
    const int lt = lid >> 3, lr = lid & 7;
    const int b = blockIdx.y >> 4, h = blockIdx.y & 15;
    const int qt = blockIdx.x, q0 = qt * 128, wq = wid * 16;
    const size_t rstride = 3 * DIM;
    const __nv_bfloat16* qh_g = qkv_hi + (size_t)b * SEQ * rstride + h * HD;
    const __nv_bfloat16* ql_g = qkv_lo + (size_t)b * SEQ * rstride + h * HD;

    #pragma unroll
    for (int t = 0; t < 2; t++) {
        const __nv_bfloat16* src = t ? ql_g : qh_g;
        #pragma unroll
        for (int i = 0; i < 4; i++) {
            const int idx = i * 256 + tid;
            const int r = idx >> 3, c = idx & 7;
            CP_ASYNC16(sb + t * FQTILE + r * FROWB + c * 16,
                       src + (size_t)(q0 + r) * rstride + c * 8);
        }
    }
    CP_COMMIT();
    CP_WAIT0();
    __syncthreads();

    uint32_t qfh[4][4], qfl[4][4];
    {
        const int row = wq + ((lt & 1) ? 8 : 0) + lr;
        #pragma unroll
        for (int kc = 0; kc < 4; kc++) {
            const int col = kc * 16 + ((lt & 2) ? 8 : 0);
            LDSM_X4(qfh[kc], sb + row * FROWB + col * 2);
            LDSM_X4(qfl[kc], sb + FQTILE + row * FROWB + col * 2);
        }
    }
    __syncthreads();

    const __nv_bfloat16* srcs[4] = { qh_g + DIM, ql_g + DIM, qh_g + 2 * DIM, ql_g + 2 * DIM };
    auto load_kv = [&](int jt, int s) {
        const int kv0 = jt * 64;
        #pragma unroll
        for (int p = 0; p < 4; p++) {
            #pragma unroll
            for (int i = 0; i < 2; i++) {
                const int idx = i * 256 + tid;
                const int r = idx >> 3, c = idx & 7;
                CP_ASYNC16(sb + s * FSTAGE + p * FTILE + r * FROWB + c * 16,
                           srcs[p] + (size_t)(kv0 + r) * rstride + c * 8);
            }
        }
        CP_COMMIT();
    };

    float m0v = -1e30f, m1v = -1e30f, l0v = 0.f, l1v = 0.f;
    float oacc[8][4] = {};

    load_kv(0, 0);

    const int krow = ((lt & 2) ? 8 : 0) + lr;
    const int kcol8 = (lt & 1) ? 8 : 0;
    const int vrow = ((lt & 1) ? 8 : 0) + lr;
    const int vcol8 = (lt & 2) ? 8 : 0;

    const int NJT = 2 * qt + 2;
    for (int jt = 0; jt < NJT; jt++) {
        const int s = jt & 1;
        __syncthreads();
        if (jt + 1 < NJT) load_kv(jt + 1, s ^ 1);
        else              CP_COMMIT();
        CP_WAIT1();
        __syncthreads();

        const uint32_t Kh = sb + s * FSTAGE;
        const uint32_t Kl = Kh + FTILE;
        const uint32_t Vh = Kh + 2 * FTILE;
        const uint32_t Vl = Kh + 3 * FTILE;

        float sacc[8][4] = {};
        #pragma unroll
        for (int kc = 0; kc < 4; kc++) {
            #pragma unroll
            for (int np = 0; np < 4; np++) {
                const uint32_t ko = (uint32_t)(np * 16 + krow) * FROWB + (kc * 16 + kcol8) * 2;
                uint32_t kb[4];
                LDSM_X4(kb, Kh + ko);
                mma16816(sacc[2 * np],     qfh[kc], kb);
                mma16816(sacc[2 * np + 1], qfh[kc], kb + 2);
                mma16816(sacc[2 * np],     qfl[kc], kb);
                mma16816(sacc[2 * np + 1], qfl[kc], kb + 2);
                LDSM_X4(kb, Kl + ko);
                mma16816(sacc[2 * np],     qfh[kc], kb);
                mma16816(sacc[2 * np + 1], qfh[kc], kb + 2);
            }
        }

        const int kv0 = jt * 64;
        const int row0 = q0 + wq + g, row1 = row0 + 8;
        if (jt >= 2 * qt) {
            #pragma unroll
            for (int j = 0; j < 8; j++) {
                const int cb = kv0 + j * 8 + tig * 2;
                if (cb > row0)     sacc[j][0] = -1e30f;
                if (cb + 1 > row0) sacc[j][1] = -1e30f;
                if (cb > row1)     sacc[j][2] = -1e30f;
                if (cb + 1 > row1) sacc[j][3] = -1e30f;
            }
        }

        float mx0 = m0v, mx1 = m1v;
        #pragma unroll
        for (int j = 0; j < 8; j++) {
            mx0 = fmaxf(mx0, fmaxf(sacc[j][0], sacc[j][1]));
            mx1 = fmaxf(mx1, fmaxf(sacc[j][2], sacc[j][3]));
        }
        mx0 = fmaxf(mx0, __shfl_xor_sync(0xFFFFFFFFu, mx0, 1));
        mx0 = fmaxf(mx0, __shfl_xor_sync(0xFFFFFFFFu, mx0, 2));
        mx1 = fmaxf(mx1, __shfl_xor_sync(0xFFFFFFFFu, mx1, 1));
        mx1 = fmaxf(mx1, __shfl_xor_sync(0xFFFFFFFFu, mx1, 2));
        const float al0 = __expf((m0v - mx0) * 0.125f);
        const float al1 = __expf((m1v - mx1) * 0.125f);
        m0v = mx0; m1v = mx1;

        float ls0 = 0.f, ls1 = 0.f;
        #pragma unroll
        for (int j = 0; j < 8; j++) {
            sacc[j][0] = __expf((sacc[j][0] - mx0) * 0.125f); ls0 += sacc[j][0];
            sacc[j][1] = __expf((sacc[j][1] - mx0) * 0.125f); ls0 += sacc[j][1];
            sacc[j][2] = __expf((sacc[j][2] - mx1) * 0.125f); ls1 += sacc[j][2];
            sacc[j][3] = __expf((sacc[j][3] - mx1) * 0.125f); ls1 += sacc[j][3];
        }
        ls0 += __shfl_xor_sync(0xFFFFFFFFu, ls0, 1);
        ls0 += __shfl_xor_sync(0xFFFFFFFFu, ls0, 2);
        ls1 += __shfl_xor_sync(0xFFFFFFFFu, ls1, 1);
        ls1 += __shfl_xor_sync(0xFFFFFFFFu, ls1, 2);
        l0v = l0v * al0 + ls0;
        l1v = l1v * al1 + ls1;

        #pragma unroll
        for (int j = 0; j < 8; j++) {
            oacc[j][0] *= al0; oacc[j][1] *= al0;
            oacc[j][2] *= al1; oacc[j][3] *= al1;
        }

        #pragma unroll
        for (int kk = 0; kk < 4; kk++) {
            uint32_t aph[4], apl[4];
            {
                __nv_bfloat16 h0, l0, h1, l1;
                split_bf16(sacc[2 * kk][0], h0, l0); split_bf16(sacc[2 * kk][1], h1, l1);
                aph[0] = pack2bf(h0, h1); apl[0] = pack2bf(l0, l1);
                split_bf16(sacc[2 * kk][2], h0, l0); split_bf16(sacc[2 * kk][3], h1, l1);
                aph[1] = pack2bf(h0, h1); apl[1] = pack2bf(l0, l1);
                split_bf16(sacc[2 * kk + 1][0], h0, l0); split_bf16(sacc[2 * kk + 1][1], h1, l1);
                aph[2] = pack2bf(h0, h1); apl[2] = pack2bf(l0, l1);
                split_bf16(sacc[2 * kk + 1][2], h0, l0); split_bf16(sacc[2 * kk + 1][3], h1, l1);
                aph[3] = pack2bf(h0, h1); apl[3] = pack2bf(l0, l1);
            }
            #pragma unroll
            for (int np = 0; np < 4; np++) {
                const uint32_t vo = (uint32_t)(kk * 16 + vrow) * FROWB + (np * 16 + vcol8) * 2;
                uint32_t vb[4];
                LDSM_X4_T(vb, Vh + vo);
                mma16816(oacc[2 * np],     aph, vb);
                mma16816(oacc[2 * np + 1], aph, vb + 2);
                mma16816(oacc[2 * np],     apl, vb);
                mma16816(oacc[2 * np + 1], apl, vb + 2);
                LDSM_X4_T(vb, Vl + vo);
                mma16816(oacc[2 * np],     aph, vb);
                mma16816(oacc[2 * np + 1], aph, vb + 2);
            }
        }
    }

    const float inv0 = 1.f / l0v, inv1 = 1.f / l1v;
    const size_t base0 = (size_t)(b * SEQ + q0 + wq + g) * DIM + h * HD;
    const size_t base1 = base0 + 8 * DIM;
    #pragma unroll
    for (int j = 0; j < 8; j++) {
        const int co = j * 8 + tig * 2;
        __nv_bfloat16 h0, lo0, h1, lo1;
        split_bf16(oacc[j][0] * inv0, h0, lo0);
        split_bf16(oacc[j][1] * inv0, h1, lo1);
        *(__nv_bfloat162*)(out_hi + base0 + co) = __nv_bfloat162(h0, h1);
        *(__nv_bfloat162*)(out_lo + base0 + co) = __nv_bfloat162(lo0, lo1);
        split_bf16(oacc[j][2] * inv1, h0, lo0);
        split_bf16(oacc[j][3] * inv1, h1, lo1);
        *(__nv_bfloat162*)(out_hi + base1 + co) = __nv_bfloat162(h0, h1);
        *(__nv_bfloat162*)(out_lo + base1 + co) = __nv_bfloat162(lo0, lo1);
    }
}

// ---------------------------------------------------------------------------
// Launch
// ---------------------------------------------------------------------------
extern "C" void kernel_launch(void* const* d_in, const int* in_sizes, int n_in,
                              void* d_out, int out_size) {
    const float* x      = (const float*)d_in[0];
    const float* ln1_g  = (const float*)d_in[1];
    const float* ln1_b  = (const float*)d_in[2];
    const float* ln2_g  = (const float*)d_in[3];
    const float* ln2_b  = (const float*)d_in[4];
    const float* W_qkv  = (const float*)d_in[5];
    const float* b_qkv  = (const float*)d_in[6];
    const float* W_proj = (const float*)d_in[7];
    const float* b_proj = (const float*)d_in[8];
    const float* W_fc   = (const float*)d_in[9];
    const float* b_fc   = (const float*)d_in[10];
    const float* W_out  = (const float*)d_in[11];
    const float* b_out  = (const float*)d_in[12];
    float* out = (float*)d_out;

    __nv_bfloat16 *h1h, *h1l, *qkvh, *qkvl, *atth, *attl;
    __nv_bfloat16 *wqh, *wql, *wph, *wpl;
    __half *h2h, *h2l, *fch, *fcl, *wfc, *wout_h;
    float *x2;
    cudaGetSymbolAddress((void**)&h1h, g_h1_hi);  cudaGetSymbolAddress((void**)&h1l, g_h1_lo);
    cudaGetSymbolAddress((void**)&qkvh, g_qkv_hi); cudaGetSymbolAddress((void**)&qkvl, g_qkv_lo);
    cudaGetSymbolAddress((void**)&atth, g_att_hi); cudaGetSymbolAddress((void**)&attl, g_att_lo);
    cudaGetSymbolAddress((void**)&x2,  g_x2);
    cudaGetSymbolAddress((void**)&h2h, g_h2_hi);  cudaGetSymbolAddress((void**)&h2l, g_h2_lo);
    cudaGetSymbolAddress((void**)&fch, g_fc_hi);  cudaGetSymbolAddress((void**)&fcl, g_fc_lo);
    cudaGetSymbolAddress((void**)&wqh, g_wqkv_hi); cudaGetSymbolAddress((void**)&wql, g_wqkv_lo);
    cudaGetSymbolAddress((void**)&wph, g_wproj_hi); cudaGetSymbolAddress((void**)&wpl, g_wproj_lo);
    cudaGetSymbolAddress((void**)&wfc, g_wfc_h);
    cudaGetSymbolAddress((void**)&wout_h, g_wout_h);

    cudaFuncSetAttribute(tc_gemm_kernel<1>, cudaFuncAttributeMaxDynamicSharedMemorySize, GEMM_SMEM);
    cudaFuncSetAttribute(tc_gemm_kernel<3>, cudaFuncAttributeMaxDynamicSharedMemorySize, GEMM_SMEM);
    cudaFuncSetAttribute(tc_gemm_h_kernel<0>, cudaFuncAttributeMaxDynamicSharedMemorySize, GEMM_SMEM_H);
    cudaFuncSetAttribute(tc_gemm_h_kernel<1>, cudaFuncAttributeMaxDynamicSharedMemorySize, GEMM_SMEM_H);
    cudaFuncSetAttribute(flash_kernel, cudaFuncAttributeMaxDynamicSharedMemorySize, FLASH_SMEM);

    // Weight conversion
    wconv_kernel<<<dim3(3 * DIM / 32, DIM / 32), 256>>>(W_qkv, wqh, wql, DIM, 3 * DIM);
    wconv_kernel<<<dim3(DIM / 32, DIM / 32), 256>>>(W_proj, wph, wpl, DIM, DIM);
    wconv_h_kernel<<<dim3(4 * DIM / 32, DIM / 32), 256>>>(W_fc, wfc, DIM, 4 * DIM);
    wconv_h_kernel<<<dim3(DIM / 32, 4 * DIM / 32), 256>>>(W_out, wout_h, 4 * DIM, DIM);

    // 1) h1 = LN1(x) -> hi/lo bf16
    ln_split_kernel<<<ROWS, 256>>>(x, ln1_g, ln1_b, h1h, h1l);

    // 2) qkv = h1 @ W_qkv + b_qkv -> hi/lo bf16 (3-pass)
    tc_gemm_kernel<3><<<dim3(3 * DIM / 128, ROWS / 128), 256, GEMM_SMEM>>>(
        h1h, h1l, wqh, wql, b_qkv, nullptr, nullptr, qkvh, qkvl, ROWS, 3 * DIM, DIM);

    // 3) att = causal_attention(qkv) -> hi/lo bf16
    flash_kernel<<<dim3(SEQ / 128, BATCH * NHEAD), 256, FLASH_SMEM>>>(qkvh, qkvl, atth, attl);

    // 4) x2 = att @ W_proj + b_proj + x (3-pass)
    tc_gemm_kernel<1><<<dim3(DIM / 128, ROWS / 128), 256, GEMM_SMEM>>>(
        atth, attl, wph, wpl, b_proj, x, x2, nullptr, nullptr, ROWS, DIM, DIM);

    // 5) h2 = LN2(x2) -> hi/lo fp16
    ln_split_h_kernel<<<ROWS, 256>>>(x2, ln2_g, ln2_b, h2h, h2l);

    // 6) fc = relu(h2 @ W_fc + b_fc) -> hi/lo fp16 (2-pass fp16)
    tc_gemm_h_kernel<1><<<dim3(4 * DIM / 128, ROWS / 128), 256, GEMM_SMEM_H>>>(
        h2h, h2l, wfc, b_fc, nullptr, nullptr, fch, fcl, ROWS, 4 * DIM, DIM);

    // 7) out = fc @ W_out + b_out + x2 (2-pass fp16)
    tc_gemm_h_kernel<0><<<dim3(DIM / 128, ROWS / 128), 256, GEMM_SMEM_H>>>(
        fch, fcl, wout_h, b_out, x2, out, nullptr, nullptr, ROWS, DIM, 4 * DIM);
}

// round 15
// speedup vs baseline: 1.3639x; 1.1576x over previous
#include <cuda_runtime.h>
#include <cuda_fp16.h>
#include <cstdint>
#include <math.h>

// Problem constants
#define DIM   1024
#define SEQ   2048
#define BATCH 2
#define NHEAD 16
#define HD    64
#define ROWS  (BATCH * SEQ)   // 4096

// ---------------------------------------------------------------------------
// PTX helpers (sm_80-portable only; no arch-'a' features)
// ---------------------------------------------------------------------------
__device__ __forceinline__ uint32_t smem_u32(const void* p) {
    uint32_t a;
    asm("{ .reg .u64 t; cvta.to.shared.u64 t, %1; cvt.u32.u64 %0, t; }" : "=r"(a) : "l"(p));
    return a;
}
#define CP_ASYNC16(sm, g) \
    asm volatile("cp.async.cg.shared.global [%0], [%1], 16;" :: "r"((uint32_t)(sm)), "l"(g) : "memory")
#define CP_COMMIT() asm volatile("cp.async.commit_group;" ::: "memory")
#define CP_WAIT1()  asm volatile("cp.async.wait_group 1;" ::: "memory")
#define CP_WAIT0()  asm volatile("cp.async.wait_group 0;" ::: "memory")

#define LDSM_X4(R, addr) \
    asm volatile("ldmatrix.sync.aligned.m8n8.x4.shared.b16 {%0,%1,%2,%3}, [%4];" \
        : "=r"((R)[0]), "=r"((R)[1]), "=r"((R)[2]), "=r"((R)[3]) : "r"((uint32_t)(addr)))
#define LDSM_X4_T(R, addr) \
    asm volatile("ldmatrix.sync.aligned.m8n8.x4.trans.shared.b16 {%0,%1,%2,%3}, [%4];" \
        : "=r"((R)[0]), "=r"((R)[1]), "=r"((R)[2]), "=r"((R)[3]) : "r"((uint32_t)(addr)))

// fp16 mma.sync m16n8k16, fp32 accumulate
__device__ __forceinline__ void mma16816h(float* c, const uint32_t* a, const uint32_t* b) {
    asm volatile(
        "mma.sync.aligned.m16n8k16.row.col.f32.f16.f16.f32 "
        "{%0,%1,%2,%3}, {%4,%5,%6,%7}, {%8,%9}, {%0,%1,%2,%3};"
        : "+f"(c[0]), "+f"(c[1]), "+f"(c[2]), "+f"(c[3])
        : "r"(a[0]), "r"(a[1]), "r"(a[2]), "r"(a[3]), "r"(b[0]), "r"(b[1]));
}

__device__ __forceinline__ uint32_t pack2h(__half a, __half b) {
    __half2 t(a, b);
    return *reinterpret_cast<uint32_t*>(&t);
}
__device__ __forceinline__ void split_fp16(float v, __half& h, __half& l) {
    h = __float2half_rn(v);
    l = __float2half_rn(v - __half2float(h));
}

// ---------------------------------------------------------------------------
// Scratch (allocation-free rule: __device__ globals)
// ---------------------------------------------------------------------------
__device__ __half g_h1_hi[ROWS * DIM];
__device__ __half g_h1_lo[ROWS * DIM];
__device__ __half g_qkv_hi[ROWS * 3 * DIM];
__device__ __half g_qkv_lo[ROWS * 3 * DIM];
__device__ __half g_att_hi[ROWS * DIM];
__device__ __half g_att_lo[ROWS * DIM];
__device__ float  g_x2   [ROWS * DIM];
__device__ __half g_h2_hi[ROWS * DIM];
__device__ __half g_h2_lo[ROWS * DIM];
__device__ __half g_fc_hi[ROWS * 4 * DIM];
__device__ __half g_fc_lo[ROWS * 4 * DIM];
// Transposed weights [N, K], single fp16
__device__ __half g_wqkv_h[3 * DIM * DIM];
__device__ __half g_wproj_h[DIM * DIM];
__device__ __half g_wfc_h [4 * DIM * DIM];
__device__ __half g_wout_h[DIM * 4 * DIM];

// ---------------------------------------------------------------------------
// Weight transpose, single fp16: W[K,N] fp32 -> Wt [N,K] fp16
// ---------------------------------------------------------------------------
__global__ void wconv_h_kernel(const float* __restrict__ W,
                               __half* __restrict__ Wt,
                               int K, int N) {
    __shared__ float t[32][33];
    const int tx = threadIdx.x & 31, ty = threadIdx.x >> 5;
    const int k0 = blockIdx.y * 32, n0 = blockIdx.x * 32;
    #pragma unroll
    for (int i = 0; i < 4; i++)
        t[ty + i * 8][tx] = W[(size_t)(k0 + ty + i * 8) * N + n0 + tx];
    __syncthreads();
    #pragma unroll
    for (int i = 0; i < 4; i++) {
        const int n = ty + i * 8;
        Wt[(size_t)(n0 + n) * K + k0 + tx] = __float2half_rn(t[tx][n]);
    }
}

// ---------------------------------------------------------------------------
// LayerNorm emitting hi/lo fp16
// ---------------------------------------------------------------------------
__global__ void ln_split_h_kernel(const float* __restrict__ x,
                                  const float* __restrict__ gamma,
                                  const float* __restrict__ beta,
                                  __half* __restrict__ hi,
                                  __half* __restrict__ lo) {
    const int row = blockIdx.x;
    const float* xr = x + (size_t)row * DIM;
    float4 v = ((const float4*)xr)[threadIdx.x];
    float s  = v.x + v.y + v.z + v.w;
    float s2 = v.x * v.x + v.y * v.y + v.z * v.z + v.w * v.w;
    #pragma unroll
    for (int o = 16; o > 0; o >>= 1) {
        s  += __shfl_down_sync(0xFFFFFFFFu, s,  o);
        s2 += __shfl_down_sync(0xFFFFFFFFu, s2, o);
    }
    __shared__ float rs[8], rs2[8];
    const int w = threadIdx.x >> 5, l = threadIdx.x & 31;
    if (l == 0) { rs[w] = s; rs2[w] = s2; }
    __syncthreads();
    if (threadIdx.x == 0) {
        float a = 0.f, b = 0.f;
        #pragma unroll
        for (int i = 0; i < 8; i++) { a += rs[i]; b += rs2[i]; }
        const float mu = a / DIM;
        rs[0] = mu; rs2[0] = b / DIM - mu * mu;
    }
    __syncthreads();
    const float mu  = rs[0];
    const float inv = rsqrtf(rs2[0] + 1e-5f);
    float4 gv = ((const float4*)gamma)[threadIdx.x];
    float4 bv = ((const float4*)beta )[threadIdx.x];
    float y0 = (v.x - mu) * inv * gv.x + bv.x;
    float y1 = (v.y - mu) * inv * gv.y + bv.y;
    float y2 = (v.z - mu) * inv * gv.z + bv.z;
    float y3 = (v.w - mu) * inv * gv.w + bv.w;
    __half h0, l0, h1, l1, h2, l2, h3, l3;
    split_fp16(y0, h0, l0); split_fp16(y1, h1, l1);
    split_fp16(y2, h2, l2); split_fp16(y3, h3, l3);
    const size_t o = (size_t)row * DIM + threadIdx.x * 4;
    *(__half2*)(hi + o)     = __half2(h0, h1);
    *(__half2*)(hi + o + 2) = __half2(h2, h3);
    *(__half2*)(lo + o)     = __half2(l0, l1);
    *(__half2*)(lo + o + 2) = __half2(l2, l3);
}

// ---------------------------------------------------------------------------
// fp16 2-pass GEMM: C[M,N] = (A_hi+A_lo)[M,K] @ B^T, B single fp16 [N,K].
// Exact in A; only error is B's fp16 rounding. 8 MMAs per i-tile.
// EPI16: 0 = fp32+bias+resid, 1 = relu(x+bias)->hi/lo, 2 = (x+bias)->hi/lo
// ---------------------------------------------------------------------------
#define ROW_B    80
#define TILE_B   (128 * ROW_B)
#define STAGE_H  (3 * TILE_B)        // Ah, Al, B
#define GEMM_SMEM_H (2 * STAGE_H)    // 61440

template <int EPI16>
__global__ void __launch_bounds__(256, 2)
tc_gemm_h_kernel(const __half* __restrict__ A_hi,
                 const __half* __restrict__ A_lo,
                 const __half* __restrict__ B,
                 const float* __restrict__ bias,
                 const float* __restrict__ resid,
                 float* __restrict__ C,
                 __half* __restrict__ C_hi,
                 __half* __restrict__ C_lo,
                 int M, int N, int K) {
    extern __shared__ char smem[];
    const uint32_t sb = smem_u32(smem);
    const int tid = threadIdx.x, wid = tid >> 5, lid = tid & 31;
    const int g = lid >> 2, tig = lid & 3;
    const int wm = (wid & 1) * 64, wn = (wid >> 1) * 32;
    const int m0 = blockIdx.y * 128, n0 = blockIdx.x * 128;

    const __half* parts[3] = { A_hi, A_lo, B };
    const int NC = K >> 5;

    auto load_chunk = [&](int kc, int s) {
        const int k0 = kc << 5;
        #pragma unroll
        for (int p = 0; p < 3; p++) {
            const __half* src = parts[p];
            const int rbase = (p < 2) ? m0 : n0;
            const uint32_t pb = sb + s * STAGE_H + p * TILE_B;
            #pragma unroll
            for (int i = 0; i < 2; i++) {
                const int idx = i * 256 + tid;
                const int r = idx >> 2, c = idx & 3;
                const __half* gp = src + (size_t)(rbase + r) * K + k0 + c * 8;
                CP_ASYNC16(pb + r * ROW_B + c * 16, gp);
            }
        }
        CP_COMMIT();
    };

    float acc[4][4][4] = {};

    load_chunk(0, 0);
    load_chunk(1, 1);

    for (int kc = 0; kc < NC; kc++) {
        CP_WAIT1();
        __syncthreads();
        const int s = kc & 1;
        const uint32_t Ah = sb + s * STAGE_H;
        const uint32_t Al = Ah + TILE_B;
        const uint32_t Bt = Ah + 2 * TILE_B;

        #pragma unroll
        for (int ks = 0; ks < 2; ks++) {
            const uint32_t kbyte = ks * 32 + tig * 4;
            uint32_t bf[4][2];
            #pragma unroll
            for (int j = 0; j < 4; j++) {
                const uint32_t ro = (uint32_t)(wn + j * 8 + g) * ROW_B + kbyte;
                bf[j][0] = *(const uint32_t*)(smem + (Bt - sb) + ro);
                bf[j][1] = *(const uint32_t*)(smem + (Bt - sb) + ro + 16);
            }
            #pragma unroll
            for (int i = 0; i < 4; i++) {
                const uint32_t ro = (uint32_t)(wm + i * 16 + g) * ROW_B + kbyte;
                uint32_t ah[4], al[4];
                ah[0] = *(const uint32_t*)(smem + (Ah - sb) + ro);
                ah[1] = *(const uint32_t*)(smem + (Ah - sb) + ro + 8 * ROW_B);
                ah[2] = *(const uint32_t*)(smem + (Ah - sb) + ro + 16);
                ah[3] = *(const uint32_t*)(smem + (Ah - sb) + ro + 8 * ROW_B + 16);
                al[0] = *(const uint32_t*)(smem + (Al - sb) + ro);
                al[1] = *(const uint32_t*)(smem + (Al - sb) + ro + 8 * ROW_B);
                al[2] = *(const uint32_t*)(smem + (Al - sb) + ro + 16);
                al[3] = *(const uint32_t*)(smem + (Al - sb) + ro + 8 * ROW_B + 16);
                #pragma unroll
                for (int j = 0; j < 4; j++) mma16816h(acc[i][j], ah, bf[j]);
                #pragma unroll
                for (int j = 0; j < 4; j++) mma16816h(acc[i][j], al, bf[j]);
            }
        }
        __syncthreads();
        if (kc + 2 < NC) load_chunk(kc + 2, s);
        else             CP_COMMIT();
    }

    // Epilogue
    #pragma unroll
    for (int i = 0; i < 4; i++) {
        const int row0 = m0 + wm + i * 16 + g;
        #pragma unroll
        for (int j = 0; j < 4; j++) {
            const int col = n0 + wn + j * 8 + tig * 2;
            const float2 b2 = *(const float2*)(bias + col);
            float v00 = acc[i][j][0] + b2.x;
            float v01 = acc[i][j][1] + b2.y;
            float v10 = acc[i][j][2] + b2.x;
            float v11 = acc[i][j][3] + b2.y;
            if (EPI16 >= 1) {
                if (EPI16 == 1) {
                    v00 = fmaxf(v00, 0.f); v01 = fmaxf(v01, 0.f);
                    v10 = fmaxf(v10, 0.f); v11 = fmaxf(v11, 0.f);
                }
                __half h0, l0, h1, l1;
                split_fp16(v00, h0, l0); split_fp16(v01, h1, l1);
                *(__half2*)(C_hi + (size_t)row0 * N + col) = __half2(h0, h1);
                *(__half2*)(C_lo + (size_t)row0 * N + col) = __half2(l0, l1);
                split_fp16(v10, h0, l0); split_fp16(v11, h1, l1);
                *(__half2*)(C_hi + (size_t)(row0 + 8) * N + col) = __half2(h0, h1);
                *(__half2*)(C_lo + (size_t)(row0 + 8) * N + col) = __half2(l0, l1);
            } else {
                const float2 r0 = *(const float2*)(resid + (size_t)row0 * N + col);
                const float2 r1 = *(const float2*)(resid + (size_t)(row0 + 8) * N + col);
                v00 += r0.x; v01 += r0.y; v10 += r1.x; v11 += r1.y;
                *(float2*)(C + (size_t)row0 * N + col)       = make_float2(v00, v01);
                *(float2*)(C + (size_t)(row0 + 8) * N + col) = make_float2(v10, v11);
            }
        }
    }
}

// ---------------------------------------------------------------------------
// Causal flash attention, fp16 mma.sync. Q exact via hi/lo split; K,V single
// fp16 (hi part only); P split hi/lo (exact). 256 threads, 128 q-rows/CTA.
// S = Qh K + Ql K (2 passes); O += Ph V + Pl V (2 passes).
// ---------------------------------------------------------------------------
#define FROWB 144                    // 128B data + 16B pad per row
#define FTILE (64 * FROWB)           // one 64-row K or V tile (9216)
#define FQTILE (128 * FROWB)         // one 128-row Q tile (18432)
#define FSTAGE (2 * FTILE)           // K, V (18432)
#define FLASH_SMEM (2 * FSTAGE)      // 36864 (= 2*FQTILE for Q staging)

__global__ void __launch_bounds__(256)
flash_kernel(const __half* __restrict__ qkv_hi,
             const __half* __restrict__ qkv_lo,
             __half* __restrict__ out_hi,
             __half* __restrict__ out_lo) {
    extern __shared__ char fsm[];
    const uint32_t sb = smem_u32(fsm);
    const int tid = threadIdx.x, wid = tid >> 5, lid = tid & 31;
    const int g = lid >> 2, tig = lid & 3;
    const int lt = lid >> 3, lr = lid & 7;
    const int b = blockIdx.y >> 4, h = blockIdx.y & 15;
    const int qt = blockIdx.x, q0 = qt * 128, wq = wid * 16;
    const size_t rstride = 3 * DIM;
    const __half* qh_g = qkv_hi + (size_t)b * SEQ * rstride + h * HD;
    const __half* ql_g = qkv_lo + (size_t)b * SEQ * rstride + h * HD;

    // ---- Stage Q hi/lo (128 rows), load A-fragments, then free the smem ----
    #pragma unroll
    for (int t = 0; t < 2; t++) {
        const __half* src = t ? ql_g : qh_g;
        #pragma unroll
        for (int i = 0; i < 4; i++) {
            const int idx = i * 256 + tid;
            const int r = idx >> 3, c = idx & 7;
            CP_ASYNC16(sb + t * FQTILE + r * FROWB + c * 16,
                       src + (size_t)(q0 + r) * rstride + c * 8);
        }
    }
    CP_COMMIT();
    CP_WAIT0();
    __syncthreads();

    uint32_t qfh[4][4], qfl[4][4];
    {
        const int row = wq + ((lt & 1) ? 8 : 0) + lr;
        #pragma unroll
        for (int kc = 0; kc < 4; kc++) {
            const int col = kc * 16 + ((lt & 2) ? 8 : 0);
            LDSM_X4(qfh[kc], sb + row * FROWB + col * 2);
            LDSM_X4(qfl[kc], sb + FQTILE + row * FROWB + col * 2);
        }
    }
    __syncthreads();

    const __half* srcs[2] = { qh_g + DIM, qh_g + 2 * DIM };  // K hi, V hi only
    auto load_kv = [&](int jt, int s) {
        const int kv0 = jt * 64;
        #pragma unroll
        for (int p = 0; p < 2; p++) {
            #pragma unroll
            for (int i = 0; i < 2; i++) {
                const int idx = i * 256 + tid;
                const int r = idx >> 3, c = idx & 7;
                CP_ASYNC16(sb + s * FSTAGE + p * FTILE + r * FROWB + c * 16,
                           srcs[p] + (size_t)(kv0 + r) * rstride + c * 8);
            }
        }
        CP_COMMIT();
    };

    float m0v = -1e30f, m1v = -1e30f, l0v = 0.f, l1v = 0.f;
    float oacc[8][4] = {};

    load_kv(0, 0);

    const int krow = ((lt & 2) ? 8 : 0) + lr;
    const int kcol8 = (lt & 1) ? 8 : 0;
    const int vrow = ((lt & 1) ? 8 : 0) + lr;
    const int vcol8 = (lt & 2) ? 8 : 0;

    const int NJT = 2 * qt + 2;                 // kv tiles covering [0, q0+128)
    for (int jt = 0; jt < NJT; jt++) {
        const int s = jt & 1;
        __syncthreads();
        if (jt + 1 < NJT) load_kv(jt + 1, s ^ 1);
        else              CP_COMMIT();
        CP_WAIT1();
        __syncthreads();

        const uint32_t Kt = sb + s * FSTAGE;
        const uint32_t Vt = Kt + FTILE;

        // ---- S = Q K^T (Qh K + Ql K) ----
        float sacc[8][4] = {};
        #pragma unroll
        for (int kc = 0; kc < 4; kc++) {
            #pragma unroll
            for (int np = 0; np < 4; np++) {
                const uint32_t ko = (uint32_t)(np * 16 + krow) * FROWB + (kc * 16 + kcol8) * 2;
                uint32_t kb[4];
                LDSM_X4(kb, Kt + ko);
                mma16816h(sacc[2 * np],     qfh[kc], kb);
                mma16816h(sacc[2 * np + 1], qfh[kc], kb + 2);
                mma16816h(sacc[2 * np],     qfl[kc], kb);
                mma16816h(sacc[2 * np + 1], qfl[kc], kb + 2);
            }
        }

        // ---- causal mask (last two kv tiles only) ----
        const int kv0 = jt * 64;
        const int row0 = q0 + wq + g, row1 = row0 + 8;
        if (jt >= 2 * qt) {
            #pragma unroll
            for (int j = 0; j < 8; j++) {
                const int cb = kv0 + j * 8 + tig * 2;
                if (cb > row0)     sacc[j][0] = -1e30f;
                if (cb + 1 > row0) sacc[j][1] = -1e30f;
                if (cb > row1)     sacc[j][2] = -1e30f;
                if (cb + 1 > row1) sacc[j][3] = -1e30f;
            }
        }

        // ---- online softmax ----
        float mx0 = m0v, mx1 = m1v;
        #pragma unroll
        for (int j = 0; j < 8; j++) {
            mx0 = fmaxf(mx0, fmaxf(sacc[j][0], sacc[j][1]));
            mx1 = fmaxf(mx1, fmaxf(sacc[j][2], sacc[j][3]));
        }
        mx0 = fmaxf(mx0, __shfl_xor_sync(0xFFFFFFFFu, mx0, 1));
        mx0 = fmaxf(mx0, __shfl_xor_sync(0xFFFFFFFFu, mx0, 2));
        mx1 = fmaxf(mx1, __shfl_xor_sync(0xFFFFFFFFu, mx1, 1));
        mx1 = fmaxf(mx1, __shfl_xor_sync(0xFFFFFFFFu, mx1, 2));
        const float al0 = __expf((m0v - mx0) * 0.125f);
        const float al1 = __expf((m1v - mx1) * 0.125f);
        m0v = mx0; m1v = mx1;

        float ls0 = 0.f, ls1 = 0.f;
        #pragma unroll
        for (int j = 0; j < 8; j++) {
            sacc[j][0] = __expf((sacc[j][0] - mx0) * 0.125f); ls0 += sacc[j][0];
            sacc[j][1] = __expf((sacc[j][1] - mx0) * 0.125f); ls0 += sacc[j][1];
            sacc[j][2] = __expf((sacc[j][2] - mx1) * 0.125f); ls1 += sacc[j][2];
            sacc[j][3] = __expf((sacc[j][3] - mx1) * 0.125f); ls1 += sacc[j][3];
        }
        ls0 += __shfl_xor_sync(0xFFFFFFFFu, ls0, 1);
        ls0 += __shfl_xor_sync(0xFFFFFFFFu, ls0, 2);
        ls1 += __shfl_xor_sync(0xFFFFFFFFu, ls1, 1);
        ls1 += __shfl_xor_sync(0xFFFFFFFFu, ls1, 2);
        l0v = l0v * al0 + ls0;
        l1v = l1v * al1 + ls1;

        #pragma unroll
        for (int j = 0; j < 8; j++) {
            oacc[j][0] *= al0; oacc[j][1] *= al0;
            oacc[j][2] *= al1; oacc[j][3] *= al1;
        }

        // ---- O += P V (Ph V + Pl V) ----
        #pragma unroll
        for (int kk = 0; kk < 4; kk++) {
            uint32_t aph[4], apl[4];
            {
                __half h0, l0, h1, l1;
                split_fp16(sacc[2 * kk][0], h0, l0); split_fp16(sacc[2 * kk][1], h1, l1);
                aph[0] = pack2h(h0, h1); apl[0] = pack2h(l0, l1);
                split_fp16(sacc[2 * kk][2], h0, l0); split_fp16(sacc[2 * kk][3], h1, l1);
                aph[1] = pack2h(h0, h1); apl[1] = pack2h(l0, l1);
                split_fp16(sacc[2 * kk + 1][0], h0, l0); split_fp16(sacc[2 * kk + 1][1], h1, l1);
                aph[2] = pack2h(h0, h1); apl[2] = pack2h(l0, l1);
                split_fp16(sacc[2 * kk + 1][2], h0, l0); split_fp16(sacc[2 * kk + 1][3], h1, l1);
                aph[3] = pack2h(h0, h1); apl[3] = pack2h(l0, l1);
            }
            #pragma unroll
            for (int np = 0; np < 4; np++) {
                const uint32_t vo = (uint32_t)(kk * 16 + vrow) * FROWB + (np * 16 + vcol8) * 2;
                uint32_t vb[4];
                LDSM_X4_T(vb, Vt + vo);
                mma16816h(oacc[2 * np],     aph, vb);
                mma16816h(oacc[2 * np + 1], aph, vb + 2);
                mma16816h(oacc[2 * np],     apl, vb);
                mma16816h(oacc[2 * np + 1], apl, vb + 2);
            }
        }
    }

    // ---- epilogue: divide by l, split hi/lo, store ----
    const float inv0 = 1.f / l0v, inv1 = 1.f / l1v;
    const size_t base0 = (size_t)(b * SEQ + q0 + wq + g) * DIM + h * HD;
    const size_t base1 = base0 + 8 * DIM;
    #pragma unroll
    for (int j = 0; j < 8; j++) {
        const int co = j * 8 + tig * 2;
        __half h0, lo0, h1, lo1;
        split_fp16(oacc[j][0] * inv0, h0, lo0);
        split_fp16(oacc[j][1] * inv0, h1, lo1);
        *(__half2*)(out_hi + base0 + co) = __half2(h0, h1);
        *(__half2*)(out_lo + base0 + co) = __half2(lo0, lo1);
        split_fp16(oacc[j][2] * inv1, h0, lo0);
        split_fp16(oacc[j][3] * inv1, h1, lo1);
        *(__half2*)(out_hi + base1 + co) = __half2(h0, h1);
        *(__half2*)(out_lo + base1 + co) = __half2(lo0, lo1);
    }
}

// ---------------------------------------------------------------------------
// Launch
// ---------------------------------------------------------------------------
extern "C" void kernel_launch(void* const* d_in, const int* in_sizes, int n_in,
                              void* d_out, int out_size) {
    const float* x      = (const float*)d_in[0];
    const float* ln1_g  = (const float*)d_in[1];
    const float* ln1_b  = (const float*)d_in[2];
    const float* ln2_g  = (const float*)d_in[3];
    const float* ln2_b  = (const float*)d_in[4];
    const float* W_qkv  = (const float*)d_in[5];
    const float* b_qkv  = (const float*)d_in[6];
    const float* W_proj = (const float*)d_in[7];
    const float* b_proj = (const float*)d_in[8];
    const float* W_fc   = (const float*)d_in[9];
    const float* b_fc   = (const float*)d_in[10];
    const float* W_out  = (const float*)d_in[11];
    const float* b_out  = (const float*)d_in[12];
    float* out = (float*)d_out;

    __half *h1h, *h1l, *qkvh, *qkvl, *atth, *attl, *h2h, *h2l, *fch, *fcl;
    __half *wq, *wp, *wfc, *wout_h;
    float *x2;
    cudaGetSymbolAddress((void**)&h1h, g_h1_hi);  cudaGetSymbolAddress((void**)&h1l, g_h1_lo);
    cudaGetSymbolAddress((void**)&qkvh, g_qkv_hi); cudaGetSymbolAddress((void**)&qkvl, g_qkv_lo);
    cudaGetSymbolAddress((void**)&atth, g_att_hi); cudaGetSymbolAddress((void**)&attl, g_att_lo);
    cudaGetSymbolAddress((void**)&x2,  g_x2);
    cudaGetSymbolAddress((void**)&h2h, g_h2_hi);  cudaGetSymbolAddress((void**)&h2l, g_h2_lo);
    cudaGetSymbolAddress((void**)&fch, g_fc_hi);  cudaGetSymbolAddress((void**)&fcl, g_fc_lo);
    cudaGetSymbolAddress((void**)&wq,  g_wqkv_h);
    cudaGetSymbolAddress((void**)&wp,  g_wproj_h);
    cudaGetSymbolAddress((void**)&wfc, g_wfc_h);
    cudaGetSymbolAddress((void**)&wout_h, g_wout_h);

    cudaFuncSetAttribute(tc_gemm_h_kernel<0>, cudaFuncAttributeMaxDynamicSharedMemorySize, GEMM_SMEM_H);
    cudaFuncSetAttribute(tc_gemm_h_kernel<1>, cudaFuncAttributeMaxDynamicSharedMemorySize, GEMM_SMEM_H);
    cudaFuncSetAttribute(tc_gemm_h_kernel<2>, cudaFuncAttributeMaxDynamicSharedMemorySize, GEMM_SMEM_H);
    cudaFuncSetAttribute(flash_kernel, cudaFuncAttributeMaxDynamicSharedMemorySize, FLASH_SMEM);

    // Weight conversion (all single fp16, transposed)
    wconv_h_kernel<<<dim3(3 * DIM / 32, DIM / 32), 256>>>(W_qkv, wq, DIM, 3 * DIM);
    wconv_h_kernel<<<dim3(DIM / 32, DIM / 32), 256>>>(W_proj, wp, DIM, DIM);
    wconv_h_kernel<<<dim3(4 * DIM / 32, DIM / 32), 256>>>(W_fc, wfc, DIM, 4 * DIM);
    wconv_h_kernel<<<dim3(DIM / 32, 4 * DIM / 32), 256>>>(W_out, wout_h, 4 * DIM, DIM);

    // 1) h1 = LN1(x) -> hi/lo fp16
    ln_split_h_kernel<<<ROWS, 256>>>(x, ln1_g, ln1_b, h1h, h1l);

    // 2) qkv = h1 @ W_qkv + b_qkv -> hi/lo fp16 (2-pass)
    tc_gemm_h_kernel<2><<<dim3(3 * DIM / 128, ROWS / 128), 256, GEMM_SMEM_H>>>(
        h1h, h1l, wq, b_qkv, nullptr, nullptr, qkvh, qkvl, ROWS, 3 * DIM, DIM);

    // 3) att = causal_attention(qkv) -> hi/lo fp16
    flash_kernel<<<dim3(SEQ / 128, BATCH * NHEAD), 256, FLASH_SMEM>>>(qkvh, qkvl, atth, attl);

    // 4) x2 = att @ W_proj + b_proj + x (2-pass)
    tc_gemm_h_kernel<0><<<dim3(DIM / 128, ROWS / 128), 256, GEMM_SMEM_H>>>(
        atth, attl, wp, b_proj, x, x2, nullptr, nullptr, ROWS, DIM, DIM);

    // 5) h2 = LN2(x2) -> hi/lo fp16
    ln_split_h_kernel<<<ROWS, 256>>>(x2, ln2_g, ln2_b, h2h, h2l);

    // 6) fc = relu(h2 @ W_fc + b_fc) -> hi/lo fp16 (2-pass)
    tc_gemm_h_kernel<1><<<dim3(4 * DIM / 128, ROWS / 128), 256, GEMM_SMEM_H>>>(
        h2h, h2l, wfc, b_fc, nullptr, nullptr, fch, fcl, ROWS, 4 * DIM, DIM);

    // 7) out = fc @ W_out + b_out + x2 (2-pass)
    tc_gemm_h_kernel<0><<<dim3(DIM / 128, ROWS / 128), 256, GEMM_SMEM_H>>>(
        fch, fcl, wout_h, b_out, x2, out, nullptr, nullptr, ROWS, DIM, 4 * DIM);
}